// round 2
// baseline (speedup 1.0000x reference)
#include <cuda_runtime.h>
#include <math.h>

#define B_ 8
#define T_ 256
#define S_ 1024
#define V_ 32000
#define L_ 2
#define GS_ 4096
#define GRID_REC 128
#define EPS_ 1e-5f

// ---------------- static device scratch (no runtime allocation) ----------
__device__ float d_xproj[(size_t)T_ * B_ * GS_];            // [T][B][4S]
__device__ float d_H0[(size_t)T_ * B_ * S_];                // [T][B][S]
__device__ float d_H1[(size_t)T_ * B_ * S_];
__device__ float d_red[2 * B_ * GRID_REC * 2];              // LN partials, dbl-buffered
__device__ unsigned d_bar[2];                               // {count, generation}

__global__ void init_bar_k(unsigned* bar) { bar[0] = 0u; bar[1] = 0u; }

// ---------------- fp32 SIMT GEMM: C[M,N] = A[M,K] @ B[N,K]^T (+bias) ------
// 128x128x8 tiles, 256 threads, 8x8 microtile, double-buffered smem.
// tok != null: A row r gathers emb row tok[(r&7)*T + (r>>3)].
// mode 0: C row-major [M,N]; mode 1: logits, row r=(t*8+b) -> out[b*T*V + t*V].
__global__ void __launch_bounds__(256, 2)
sgemm_nt(int M, int N, int K,
         const float* __restrict__ A, const int* __restrict__ tok,
         const float* __restrict__ Bm, const float* __restrict__ bias,
         float* __restrict__ C, int mode)
{
    __shared__ float As[2][8 * 128];
    __shared__ float Bs[2][8 * 128];
    const int tid = threadIdx.x;
    const int n0 = blockIdx.x * 128;
    const int m0 = blockIdx.y * 128;
    const int lr = tid >> 1;              // 0..127
    const int lk = (tid & 1) * 4;         // 0 or 4

    const float* Arow;
    {
        int m = m0 + lr;
        if (tok) {
            int bb = m & 7, tt = m >> 3;
            Arow = A + (size_t)__ldg(&tok[bb * T_ + tt]) * K;
        } else {
            Arow = A + (size_t)m * K;
        }
    }
    const float* Brow = Bm + (size_t)(n0 + lr) * K;

    {   // stage 0
        float4 av = *(const float4*)(Arow + lk);
        float4 bv = *(const float4*)(Brow + lk);
        As[0][(lk + 0) * 128 + lr] = av.x; As[0][(lk + 1) * 128 + lr] = av.y;
        As[0][(lk + 2) * 128 + lr] = av.z; As[0][(lk + 3) * 128 + lr] = av.w;
        Bs[0][(lk + 0) * 128 + lr] = bv.x; Bs[0][(lk + 1) * 128 + lr] = bv.y;
        Bs[0][(lk + 2) * 128 + lr] = bv.z; Bs[0][(lk + 3) * 128 + lr] = bv.w;
    }
    __syncthreads();

    const int tx = tid & 15, ty = tid >> 4;
    float acc[8][8];
    #pragma unroll
    for (int i = 0; i < 8; ++i)
        #pragma unroll
        for (int j = 0; j < 8; ++j) acc[i][j] = 0.f;

    int cur = 0;
    const int KT = K >> 3;
    for (int kt = 0; kt < KT; ++kt) {
        float4 an, bn;
        bool more = (kt + 1 < KT);
        if (more) {
            an = *(const float4*)(Arow + (kt + 1) * 8 + lk);
            bn = *(const float4*)(Brow + (kt + 1) * 8 + lk);
        }
        #pragma unroll
        for (int kk = 0; kk < 8; ++kk) {
            float4 a0 = *(const float4*)&As[cur][kk * 128 + ty * 4];
            float4 a1 = *(const float4*)&As[cur][kk * 128 + 64 + ty * 4];
            float4 b0 = *(const float4*)&Bs[cur][kk * 128 + tx * 4];
            float4 b1 = *(const float4*)&Bs[cur][kk * 128 + 64 + tx * 4];
            float ar[8] = {a0.x, a0.y, a0.z, a0.w, a1.x, a1.y, a1.z, a1.w};
            float br[8] = {b0.x, b0.y, b0.z, b0.w, b1.x, b1.y, b1.z, b1.w};
            #pragma unroll
            for (int i = 0; i < 8; ++i)
                #pragma unroll
                for (int j = 0; j < 8; ++j)
                    acc[i][j] += ar[i] * br[j];
        }
        if (more) {
            int nxt = cur ^ 1;
            As[nxt][(lk + 0) * 128 + lr] = an.x; As[nxt][(lk + 1) * 128 + lr] = an.y;
            As[nxt][(lk + 2) * 128 + lr] = an.z; As[nxt][(lk + 3) * 128 + lr] = an.w;
            Bs[nxt][(lk + 0) * 128 + lr] = bn.x; Bs[nxt][(lk + 1) * 128 + lr] = bn.y;
            Bs[nxt][(lk + 2) * 128 + lr] = bn.z; Bs[nxt][(lk + 3) * 128 + lr] = bn.w;
            __syncthreads();
            cur = nxt;
        }
    }

    float4 bv0 = make_float4(0.f, 0.f, 0.f, 0.f), bv1 = bv0;
    if (bias) {
        bv0 = *(const float4*)&bias[n0 + tx * 4];
        bv1 = *(const float4*)&bias[n0 + 64 + tx * 4];
    }
    #pragma unroll
    for (int i = 0; i < 8; ++i) {
        int ml = (i < 4) ? (ty * 4 + i) : (64 + ty * 4 + (i - 4));
        int m = m0 + ml;
        float* crow;
        if (mode == 0) {
            crow = C + (size_t)m * N;
        } else {
            int tt = m >> 3, bb = m & 7;
            crow = C + (size_t)bb * ((size_t)T_ * V_) + (size_t)tt * V_;
        }
        float4 v0 = make_float4(acc[i][0] + bv0.x, acc[i][1] + bv0.y,
                                acc[i][2] + bv0.z, acc[i][3] + bv0.w);
        float4 v1 = make_float4(acc[i][4] + bv1.x, acc[i][5] + bv1.y,
                                acc[i][6] + bv1.z, acc[i][7] + bv1.w);
        *(float4*)(crow + n0 + tx * 4)      = v0;
        *(float4*)(crow + n0 + 64 + tx * 4) = v1;
    }
}

// ---------------- persistent recurrence: one layer, all T steps -----------
// 128 blocks x 256 threads. Block owns 8 state columns (s0..s0+7) -> 32 gate
// rows of Wh pinned in SMEM. One grid barrier per timestep handles both the
// h broadcast and the cross-block LayerNorm reduction.
#define REC_FLOATS (32*1024 + 8*1024 + 256 + 64 + 64 + 64 + 16 + 16 + 128)
#define REC_BYTES  (REC_FLOATS * 4)

__device__ __forceinline__ void grid_barrier(unsigned* bar) {
    __syncthreads();
    if (threadIdx.x == 0) {
        __threadfence();
        unsigned g = *((volatile unsigned*)&bar[1]);
        if (atomicAdd(&bar[0], 1u) == GRID_REC - 1) {
            bar[0] = 0u;
            __threadfence();
            atomicAdd(&bar[1], 1u);
        } else {
            while (*((volatile unsigned*)&bar[1]) == g) { }
        }
    }
    __syncthreads();
}

__device__ __forceinline__ float sigmf(float x) { return 1.f / (1.f + expf(-x)); }

__global__ void __launch_bounds__(256, 1)
lstm_rec(const float* __restrict__ xproj,   // [T][B][4S]
         const float* __restrict__ Wh,      // [4S][S]
         const float* __restrict__ gamma, const float* __restrict__ beta,
         float* __restrict__ H,             // [T][B][S]
         float* __restrict__ hfin, float* __restrict__ cfin,  // [B][S] each
         float* __restrict__ red, unsigned* __restrict__ bar)
{
    extern __shared__ float smem[];
    float* Wh_s  = smem;                 // 32*1024
    float* h_s   = Wh_s + 32 * 1024;     // 8*1024  ([b][S])
    float* gbuf  = h_s + 8 * 1024;       // 32 cols x 8 b
    float* craw  = gbuf + 256;           // 64 ([u][b])
    float* hbuf  = craw + 64;            // 64
    float* cnorm = hbuf + 64;            // 64
    float* gmb   = cnorm + 64;           // gamma[8] | beta[8]
    float* stat  = gmb + 16;             // mu[8] | rstd[8]
    float* part  = stat + 16;            // 64 x 2

    const int tid = threadIdx.x;
    const int blk = blockIdx.x;
    const int s0  = blk * 8;

    {   // load Wh slice: smem row (g*8+u) <- Wh row (g*S + s0 + u)
        int r = tid >> 3, ch = tid & 7;
        int g = r >> 3, u = r & 7;
        const float4* src = (const float4*)(Wh + (size_t)(g * S_ + s0 + u) * S_) + ch * 32;
        float4* dst = (float4*)(Wh_s + r * S_) + ch * 32;
        #pragma unroll 8
        for (int i = 0; i < 32; ++i) dst[i] = __ldg(src + i);
    }
    if (tid < 8)  { gmb[tid] = __ldg(&gamma[s0 + tid]); gmb[8 + tid] = __ldg(&beta[s0 + tid]); }
    if (tid < 64) cnorm[tid] = 0.f;
    gbuf[tid] = 0.f;
    __syncthreads();

    const int w = tid >> 5, lane = tid & 31;
    const int cl0 = w * 4;

    for (int t = 0; t < T_; ++t) {
        if (t > 0) {   // broadcast h(t-1) (written by all blocks, via L2)
            const float4* hsrc = (const float4*)(H + (size_t)(t - 1) * (B_ * S_));
            float4* hd = (float4*)h_s;
            #pragma unroll
            for (int j = 0; j < 8; ++j)
                hd[tid + j * 256] = __ldcg(hsrc + tid + j * 256);
            __syncthreads();

            // warp-split-K dot: 4 gate cols x 8 batches per warp
            float acc[4][8];
            #pragma unroll
            for (int c = 0; c < 4; ++c)
                #pragma unroll
                for (int b = 0; b < 8; ++b) acc[c][b] = 0.f;
            #pragma unroll
            for (int i = 0; i < 8; ++i) {
                int k = (lane << 2) + (i << 7);
                float4 hv[8];
                #pragma unroll
                for (int b = 0; b < 8; ++b)
                    hv[b] = *(const float4*)(h_s + b * S_ + k);
                #pragma unroll
                for (int c = 0; c < 4; ++c) {
                    float4 wv = *(const float4*)(Wh_s + (cl0 + c) * S_ + k);
                    #pragma unroll
                    for (int b = 0; b < 8; ++b)
                        acc[c][b] += wv.x * hv[b].x + wv.y * hv[b].y +
                                     wv.z * hv[b].z + wv.w * hv[b].w;
                }
            }
            #pragma unroll
            for (int c = 0; c < 4; ++c)
                #pragma unroll
                for (int b = 0; b < 8; ++b) {
                    float v = acc[c][b];
                    v += __shfl_xor_sync(0xffffffffu, v, 16);
                    v += __shfl_xor_sync(0xffffffffu, v, 8);
                    v += __shfl_xor_sync(0xffffffffu, v, 4);
                    v += __shfl_xor_sync(0xffffffffu, v, 2);
                    v += __shfl_xor_sync(0xffffffffu, v, 1);
                    if (lane == 0) gbuf[(cl0 + c) * 8 + b] = v;
                }
        }
        __syncthreads();

        if (tid < 64) {   // gates + cell/hidden update for 8 units x 8 batches
            int u = tid >> 3, b = tid & 7;
            const float* xp = xproj + (size_t)(t * B_ + b) * GS_ + s0 + u;
            float pi = __ldg(xp + 0 * S_) + gbuf[(0 * 8 + u) * 8 + b];
            float pf = __ldg(xp + 1 * S_) + gbuf[(1 * 8 + u) * 8 + b];
            float po = __ldg(xp + 2 * S_) + gbuf[(2 * 8 + u) * 8 + b];
            float pg = __ldg(xp + 3 * S_) + gbuf[(3 * 8 + u) * 8 + b];
            float ig = sigmf(pi), fg = sigmf(pf), og = sigmf(po), gg = tanhf(pg);
            float cr = fg * cnorm[tid] + ig * gg;
            float hh = og * tanhf(cr);           // pre-norm cell for hidden
            craw[tid] = cr;
            hbuf[tid] = hh;
            H[(size_t)t * (B_ * S_) + b * S_ + s0 + u] = hh;
        }
        __syncthreads();

        int par = t & 1;
        if (tid < 8) {   // per-block LN partials for batch b=tid
            float s1 = 0.f, s2 = 0.f;
            #pragma unroll
            for (int u = 0; u < 8; ++u) { float v = craw[u * 8 + tid]; s1 += v; s2 += v * v; }
            float2* rp = (float2*)(red + ((size_t)par * B_ + tid) * (GRID_REC * 2) + blk * 2);
            *rp = make_float2(s1, s2);
        }

        grid_barrier(bar);   // publishes H[t] + red

        {   // reduce 128 partials per batch
            const float* rp = red + (size_t)par * B_ * GRID_REC * 2;
            if (tid < 64) {
                int b = tid >> 3, seg = tid & 7;
                float s1 = 0.f, s2 = 0.f;
                #pragma unroll
                for (int q = 0; q < 16; ++q) {
                    float2 v = __ldcg((const float2*)(rp + ((size_t)b * GRID_REC + seg * 16 + q) * 2));
                    s1 += v.x; s2 += v.y;
                }
                part[tid * 2] = s1; part[tid * 2 + 1] = s2;
            }
            __syncthreads();
            if (tid < 8) {
                float s1 = 0.f, s2 = 0.f;
                #pragma unroll
                for (int seg = 0; seg < 8; ++seg) {
                    s1 += part[(tid * 8 + seg) * 2];
                    s2 += part[(tid * 8 + seg) * 2 + 1];
                }
                float mu = s1 * (1.f / (float)S_);
                float var = s2 * (1.f / (float)S_) - mu * mu;
                stat[tid] = mu; stat[8 + tid] = rsqrtf(var + EPS_);
            }
            __syncthreads();
        }

        if (tid < 64) {   // normalize carried cell
            int u = tid >> 3, b = tid & 7;
            float cn = (craw[tid] - stat[b]) * stat[8 + b] * gmb[u] + gmb[8 + u];
            cnorm[tid] = cn;
            if (t == T_ - 1) {
                cfin[b * S_ + s0 + u] = cn;
                hfin[b * S_ + s0 + u] = hbuf[tid];
            }
        }
        __syncthreads();
    }
}

// ---------------- host launcher -------------------------------------------
extern "C" void kernel_launch(void* const* d_in, const int* in_sizes, int n_in,
                              void* d_out, int out_size)
{
    (void)in_sizes; (void)n_in; (void)out_size;
    const int*   x     = (const int*)d_in[0];
    const float* emb   = (const float*)d_in[1];
    const float* Wx    = (const float*)d_in[2];
    const float* Wh    = (const float*)d_in[3];
    const float* gamma = (const float*)d_in[4];
    const float* beta  = (const float*)d_in[5];
    const float* Wout  = (const float*)d_in[6];
    const float* bout  = (const float*)d_in[7];
    float* out = (float*)d_out;

    float *xproj, *H0, *H1, *red;
    unsigned* bar;
    cudaGetSymbolAddress((void**)&xproj, d_xproj);
    cudaGetSymbolAddress((void**)&H0,    d_H0);
    cudaGetSymbolAddress((void**)&H1,    d_H1);
    cudaGetSymbolAddress((void**)&red,   d_red);
    cudaGetSymbolAddress((void**)&bar,   d_bar);

    cudaFuncSetAttribute(lstm_rec, cudaFuncAttributeMaxDynamicSharedMemorySize, REC_BYTES);

    float* h_out = out + (size_t)B_ * T_ * V_;
    float* c_out = h_out + (size_t)L_ * B_ * S_;

    const size_t wstride = (size_t)GS_ * S_;

    init_bar_k<<<1, 1>>>(bar);

    // layer 0: xproj = gather(emb, x) @ Wx0^T
    sgemm_nt<<<dim3(GS_ / 128, (T_ * B_) / 128), 256>>>(
        T_ * B_, GS_, S_, emb, x, Wx, nullptr, xproj, 0);
    lstm_rec<<<GRID_REC, 256, REC_BYTES>>>(
        xproj, Wh, gamma, beta, H0,
        h_out, c_out, red, bar);

    // layer 1: xproj = H0 @ Wx1^T
    sgemm_nt<<<dim3(GS_ / 128, (T_ * B_) / 128), 256>>>(
        T_ * B_, GS_, S_, H0, nullptr, Wx + wstride, nullptr, xproj, 0);
    lstm_rec<<<GRID_REC, 256, REC_BYTES>>>(
        xproj, Wh + wstride, gamma + S_, beta + S_, H1,
        h_out + (size_t)B_ * S_, c_out + (size_t)B_ * S_, red, bar);

    // logits: out = H1 @ Wout^T + bout
    sgemm_nt<<<dim3(V_ / 128, (T_ * B_) / 128), 256>>>(
        T_ * B_, V_, S_, H1, nullptr, Wout, bout, out, 1);
}

// round 3
// speedup vs baseline: 1.0806x; 1.0806x over previous
#include <cuda_runtime.h>
#include <cuda_bf16.h>
#include <math.h>

#define B_ 8
#define T_ 256
#define S_ 1024
#define V_ 32000
#define L_ 2
#define GS_ 4096
#define GRID_REC 128
#define EPS_ 1e-5f

// ---------------- static device scratch (no runtime allocation) ----------
__device__ float d_xproj[(size_t)T_ * B_ * GS_];            // [T][B][4S]
__device__ float d_H0[(size_t)T_ * B_ * S_];                // [T][B][S]
__device__ float d_H1[(size_t)T_ * B_ * S_];
__device__ float d_red[2 * B_ * GRID_REC * 2];              // LN partials, dbl-buffered
__device__ unsigned d_bar[2];                               // {count, generation}

__global__ void init_bar_k(unsigned* bar) { bar[0] = 0u; bar[1] = 0u; }

// =====================================================================
// bf16-split tensor-core GEMM: C[M,N] = A[M,K] @ B[N,K]^T (+bias)
// A,B fp32 in global; split to bf16 hi/lo at SMEM store; 3-term mma
// (AhBh + AhBl + AlBh) with fp32 accumulators => ~fp32 precision.
// Block: 256 thr (8 warps, 2x4), tile 128x128, K-step 32, double-buffered.
// tok != null: A row r gathers emb row tok[(r&7)*T + (r>>3)].
// mode 0: C row-major [M,N]; mode 1: logits row r=(t*8+b) -> out[b*T*V+t*V].
// =====================================================================

#define SWZ(r, w) ((w) ^ ((r) & 7) ^ (((r) >> 3) & 3))

__device__ __forceinline__ unsigned pack_hi(float x, float y, float& rx, float& ry) {
    __nv_bfloat16 bx = __float2bfloat16(x);
    __nv_bfloat16 by = __float2bfloat16(y);
    rx = x - __bfloat162float(bx);
    ry = y - __bfloat162float(by);
    __nv_bfloat162 p; p.x = bx; p.y = by;
    return *reinterpret_cast<unsigned*>(&p);
}
__device__ __forceinline__ unsigned pack_lo(float x, float y) {
    __nv_bfloat162 p; p.x = __float2bfloat16(x); p.y = __float2bfloat16(y);
    return *reinterpret_cast<unsigned*>(&p);
}

__device__ __forceinline__ void mma16816(float* c, const unsigned* a, const unsigned* b) {
    asm volatile(
        "mma.sync.aligned.m16n8k16.row.col.f32.bf16.bf16.f32 "
        "{%0,%1,%2,%3}, {%4,%5,%6,%7}, {%8,%9}, {%0,%1,%2,%3};\n"
        : "+f"(c[0]), "+f"(c[1]), "+f"(c[2]), "+f"(c[3])
        : "r"(a[0]), "r"(a[1]), "r"(a[2]), "r"(a[3]), "r"(b[0]), "r"(b[1]));
}

// convert 32 floats (one row's K32 slice) and store hi/lo to smem stage
__device__ __forceinline__ void store_cvt(unsigned* sm, int stage, unsigned zh,
                                          int r, const float4* v) {
    unsigned base = (unsigned)stage * 8192u + zh;
    #pragma unroll
    for (int i = 0; i < 8; ++i) {
        int c = i >> 2;            // k16 chunk
        int wb = (i & 3) * 2;      // word base within chunk row
        float lx0, ly0, lx1, ly1;
        unsigned h0 = pack_hi(v[i].x, v[i].y, lx0, ly0);
        unsigned h1 = pack_hi(v[i].z, v[i].w, lx1, ly1);
        unsigned l0 = pack_lo(lx0, ly0);
        unsigned l1 = pack_lo(lx1, ly1);
        unsigned rowoff = (unsigned)(c * 1024 + r * 8);
        sm[base + rowoff + SWZ(r, wb)]     = h0;
        sm[base + rowoff + SWZ(r, wb + 1)] = h1;
        sm[base + 2048u + rowoff + SWZ(r, wb)]     = l0;
        sm[base + 2048u + rowoff + SWZ(r, wb + 1)] = l1;
    }
}

__global__ void __launch_bounds__(256)
gemm_bf16s(int M, int N, int K,
           const float* __restrict__ A, const int* __restrict__ tok,
           const float* __restrict__ Bm, const float* __restrict__ bias,
           float* __restrict__ C, int mode)
{
    extern __shared__ unsigned sm[];          // 2 stages x 8192 words = 64KB
    const int tid = threadIdx.x;
    const int n0 = blockIdx.x * 128;
    const int m0 = blockIdx.y * 128;

    // ---- loader role: one row (A or B) per thread ----
    const int lr = tid & 127;
    const int isB = tid >> 7;
    const float* src;
    if (isB) {
        src = Bm + (size_t)(n0 + lr) * K;
    } else {
        int m = m0 + lr;
        if (tok) src = A + (size_t)__ldg(&tok[(m & 7) * T_ + (m >> 3)]) * K;
        else     src = A + (size_t)m * K;
    }
    const unsigned zh = isB ? 4096u : 0u;

    // ---- compute role coords ----
    const int wid = tid >> 5, lane = tid & 31;
    const int warp_m = wid >> 2, warp_n = wid & 3;
    const int m_base = warp_m * 64, n_base = warp_n * 32;
    const int g = lane >> 2, q = lane & 3;

    float acc[4][4][4];
    #pragma unroll
    for (int i = 0; i < 4; ++i)
        #pragma unroll
        for (int j = 0; j < 4; ++j)
            #pragma unroll
            for (int k = 0; k < 4; ++k) acc[i][j][k] = 0.f;

    // prologue: stage 0
    {
        float4 v[8];
        #pragma unroll
        for (int i = 0; i < 8; ++i) v[i] = __ldg((const float4*)src + i);
        store_cvt(sm, 0, zh, lr, v);
    }
    __syncthreads();

    const int KT = K >> 5;   // K32 steps
    for (int kt = 0; kt < KT; ++kt) {
        const int cur = kt & 1;
        float4 v[8];
        const bool more = (kt + 1 < KT);
        if (more) {
            const float4* gsrc = (const float4*)(src + (size_t)(kt + 1) * 32);
            #pragma unroll
            for (int i = 0; i < 8; ++i) v[i] = __ldg(gsrc + i);
        }

        const unsigned* sA = sm + (unsigned)cur * 8192u;
        const unsigned* sB = sA + 4096u;

        #pragma unroll
        for (int c = 0; c < 2; ++c) {
            unsigned bh[4][2], bl[4][2];
            #pragma unroll
            for (int fn = 0; fn < 4; ++fn) {
                int rn = n_base + fn * 8 + g;
                unsigned off = (unsigned)(c * 1024 + rn * 8);
                bh[fn][0] = sB[off + SWZ(rn, q)];
                bh[fn][1] = sB[off + SWZ(rn, q + 4)];
                bl[fn][0] = sB[2048u + off + SWZ(rn, q)];
                bl[fn][1] = sB[2048u + off + SWZ(rn, q + 4)];
            }
            #pragma unroll
            for (int fm = 0; fm < 4; ++fm) {
                int r0 = m_base + fm * 16 + g, r1 = r0 + 8;
                unsigned o0 = (unsigned)(c * 1024 + r0 * 8);
                unsigned o1 = (unsigned)(c * 1024 + r1 * 8);
                unsigned ah[4], al[4];
                ah[0] = sA[o0 + SWZ(r0, q)];
                ah[1] = sA[o1 + SWZ(r1, q)];
                ah[2] = sA[o0 + SWZ(r0, q + 4)];
                ah[3] = sA[o1 + SWZ(r1, q + 4)];
                al[0] = sA[2048u + o0 + SWZ(r0, q)];
                al[1] = sA[2048u + o1 + SWZ(r1, q)];
                al[2] = sA[2048u + o0 + SWZ(r0, q + 4)];
                al[3] = sA[2048u + o1 + SWZ(r1, q + 4)];
                #pragma unroll
                for (int fn = 0; fn < 4; ++fn) {
                    mma16816(acc[fm][fn], ah, bh[fn]);   // hi*hi
                    mma16816(acc[fm][fn], ah, bl[fn]);   // hi*lo
                    mma16816(acc[fm][fn], al, bh[fn]);   // lo*hi
                }
            }
        }

        if (more) store_cvt(sm, cur ^ 1, zh, lr, v);
        __syncthreads();
    }

    // ---- epilogue ----
    #pragma unroll
    for (int fm = 0; fm < 4; ++fm) {
        int row0 = m0 + m_base + fm * 16 + g;
        int row1 = row0 + 8;
        float *p0, *p1;
        if (mode == 0) {
            p0 = C + (size_t)row0 * N;
            p1 = C + (size_t)row1 * N;
        } else {
            p0 = C + (size_t)(row0 & 7) * ((size_t)T_ * V_) + (size_t)(row0 >> 3) * V_;
            p1 = C + (size_t)(row1 & 7) * ((size_t)T_ * V_) + (size_t)(row1 >> 3) * V_;
        }
        #pragma unroll
        for (int fn = 0; fn < 4; ++fn) {
            int col = n0 + n_base + fn * 8 + q * 2;
            float b0 = 0.f, b1 = 0.f;
            if (bias) { b0 = __ldg(&bias[col]); b1 = __ldg(&bias[col + 1]); }
            float2 v0 = make_float2(acc[fm][fn][0] + b0, acc[fm][fn][1] + b1);
            float2 v1 = make_float2(acc[fm][fn][2] + b0, acc[fm][fn][3] + b1);
            *(float2*)(p0 + col) = v0;
            *(float2*)(p1 + col) = v1;
        }
    }
}

// ---------------- persistent recurrence: one layer, all T steps -----------
#define REC_FLOATS (32*1024 + 8*1024 + 256 + 64 + 64 + 64 + 16 + 16 + 128)
#define REC_BYTES  (REC_FLOATS * 4)

__device__ __forceinline__ void grid_barrier(unsigned* bar) {
    __syncthreads();
    if (threadIdx.x == 0) {
        __threadfence();
        unsigned g = *((volatile unsigned*)&bar[1]);
        if (atomicAdd(&bar[0], 1u) == GRID_REC - 1) {
            bar[0] = 0u;
            __threadfence();
            atomicAdd(&bar[1], 1u);
        } else {
            while (*((volatile unsigned*)&bar[1]) == g) { }
        }
    }
    __syncthreads();
}

__device__ __forceinline__ float sigmf(float x) { return 1.f / (1.f + expf(-x)); }

__global__ void __launch_bounds__(256, 1)
lstm_rec(const float* __restrict__ xproj,   // [T][B][4S]
         const float* __restrict__ Wh,      // [4S][S]
         const float* __restrict__ gamma, const float* __restrict__ beta,
         float* __restrict__ H,             // [T][B][S]
         float* __restrict__ hfin, float* __restrict__ cfin,  // [B][S] each
         float* __restrict__ red, unsigned* __restrict__ bar)
{
    extern __shared__ float smem[];
    float* Wh_s  = smem;                 // 32*1024
    float* h_s   = Wh_s + 32 * 1024;     // 8*1024  ([b][S])
    float* gbuf  = h_s + 8 * 1024;       // 32 cols x 8 b
    float* craw  = gbuf + 256;           // 64 ([u][b])
    float* hbuf  = craw + 64;            // 64
    float* cnorm = hbuf + 64;            // 64
    float* gmb   = cnorm + 64;           // gamma[8] | beta[8]
    float* stat  = gmb + 16;             // mu[8] | rstd[8]
    float* part  = stat + 16;            // 64 x 2

    const int tid = threadIdx.x;
    const int blk = blockIdx.x;
    const int s0  = blk * 8;

    {   // load Wh slice: smem row (g*8+u) <- Wh row (g*S + s0 + u)
        int r = tid >> 3, ch = tid & 7;
        int g = r >> 3, u = r & 7;
        const float4* src = (const float4*)(Wh + (size_t)(g * S_ + s0 + u) * S_) + ch * 32;
        float4* dst = (float4*)(Wh_s + r * S_) + ch * 32;
        #pragma unroll 8
        for (int i = 0; i < 32; ++i) dst[i] = __ldg(src + i);
    }
    if (tid < 8)  { gmb[tid] = __ldg(&gamma[s0 + tid]); gmb[8 + tid] = __ldg(&beta[s0 + tid]); }
    if (tid < 64) cnorm[tid] = 0.f;
    gbuf[tid] = 0.f;
    __syncthreads();

    const int w = tid >> 5, lane = tid & 31;
    const int cl0 = w * 4;

    for (int t = 0; t < T_; ++t) {
        if (t > 0) {   // broadcast h(t-1) (written by all blocks, via L2)
            const float4* hsrc = (const float4*)(H + (size_t)(t - 1) * (B_ * S_));
            float4* hd = (float4*)h_s;
            #pragma unroll
            for (int j = 0; j < 8; ++j)
                hd[tid + j * 256] = __ldcg(hsrc + tid + j * 256);
            __syncthreads();

            // warp-split-K dot: 4 gate cols x 8 batches per warp
            float acc[4][8];
            #pragma unroll
            for (int c = 0; c < 4; ++c)
                #pragma unroll
                for (int b = 0; b < 8; ++b) acc[c][b] = 0.f;
            #pragma unroll
            for (int i = 0; i < 8; ++i) {
                int k = (lane << 2) + (i << 7);
                float4 hv[8];
                #pragma unroll
                for (int b = 0; b < 8; ++b)
                    hv[b] = *(const float4*)(h_s + b * S_ + k);
                #pragma unroll
                for (int c = 0; c < 4; ++c) {
                    float4 wv = *(const float4*)(Wh_s + (cl0 + c) * S_ + k);
                    #pragma unroll
                    for (int b = 0; b < 8; ++b)
                        acc[c][b] += wv.x * hv[b].x + wv.y * hv[b].y +
                                     wv.z * hv[b].z + wv.w * hv[b].w;
                }
            }
            #pragma unroll
            for (int c = 0; c < 4; ++c)
                #pragma unroll
                for (int b = 0; b < 8; ++b) {
                    float v = acc[c][b];
                    v += __shfl_xor_sync(0xffffffffu, v, 16);
                    v += __shfl_xor_sync(0xffffffffu, v, 8);
                    v += __shfl_xor_sync(0xffffffffu, v, 4);
                    v += __shfl_xor_sync(0xffffffffu, v, 2);
                    v += __shfl_xor_sync(0xffffffffu, v, 1);
                    if (lane == 0) gbuf[(cl0 + c) * 8 + b] = v;
                }
        }
        __syncthreads();

        if (tid < 64) {   // gates + cell/hidden update for 8 units x 8 batches
            int u = tid >> 3, b = tid & 7;
            const float* xp = xproj + (size_t)(t * B_ + b) * GS_ + s0 + u;
            float pi = __ldg(xp + 0 * S_) + gbuf[(0 * 8 + u) * 8 + b];
            float pf = __ldg(xp + 1 * S_) + gbuf[(1 * 8 + u) * 8 + b];
            float po = __ldg(xp + 2 * S_) + gbuf[(2 * 8 + u) * 8 + b];
            float pg = __ldg(xp + 3 * S_) + gbuf[(3 * 8 + u) * 8 + b];
            float ig = sigmf(pi), fg = sigmf(pf), og = sigmf(po), gg = tanhf(pg);
            float cr = fg * cnorm[tid] + ig * gg;
            float hh = og * tanhf(cr);           // pre-norm cell for hidden
            craw[tid] = cr;
            hbuf[tid] = hh;
            H[(size_t)t * (B_ * S_) + b * S_ + s0 + u] = hh;
        }
        __syncthreads();

        int par = t & 1;
        if (tid < 8) {   // per-block LN partials for batch b=tid
            float s1 = 0.f, s2 = 0.f;
            #pragma unroll
            for (int u = 0; u < 8; ++u) { float v = craw[u * 8 + tid]; s1 += v; s2 += v * v; }
            float2* rp = (float2*)(red + ((size_t)par * B_ + tid) * (GRID_REC * 2) + blk * 2);
            *rp = make_float2(s1, s2);
        }

        grid_barrier(bar);   // publishes H[t] + red

        {   // reduce 128 partials per batch
            const float* rp = red + (size_t)par * B_ * GRID_REC * 2;
            if (tid < 64) {
                int b = tid >> 3, seg = tid & 7;
                float s1 = 0.f, s2 = 0.f;
                #pragma unroll
                for (int q = 0; q < 16; ++q) {
                    float2 v = __ldcg((const float2*)(rp + ((size_t)b * GRID_REC + seg * 16 + q) * 2));
                    s1 += v.x; s2 += v.y;
                }
                part[tid * 2] = s1; part[tid * 2 + 1] = s2;
            }
            __syncthreads();
            if (tid < 8) {
                float s1 = 0.f, s2 = 0.f;
                #pragma unroll
                for (int seg = 0; seg < 8; ++seg) {
                    s1 += part[(tid * 8 + seg) * 2];
                    s2 += part[(tid * 8 + seg) * 2 + 1];
                }
                float mu = s1 * (1.f / (float)S_);
                float var = s2 * (1.f / (float)S_) - mu * mu;
                stat[tid] = mu; stat[8 + tid] = rsqrtf(var + EPS_);
            }
            __syncthreads();
        }

        if (tid < 64) {   // normalize carried cell
            int u = tid >> 3, b = tid & 7;
            float cn = (craw[tid] - stat[b]) * stat[8 + b] * gmb[u] + gmb[8 + u];
            cnorm[tid] = cn;
            if (t == T_ - 1) {
                cfin[b * S_ + s0 + u] = cn;
                hfin[b * S_ + s0 + u] = hbuf[tid];
            }
        }
        __syncthreads();
    }
}

// ---------------- host launcher -------------------------------------------
extern "C" void kernel_launch(void* const* d_in, const int* in_sizes, int n_in,
                              void* d_out, int out_size)
{
    (void)in_sizes; (void)n_in; (void)out_size;
    const int*   x     = (const int*)d_in[0];
    const float* emb   = (const float*)d_in[1];
    const float* Wx    = (const float*)d_in[2];
    const float* Wh    = (const float*)d_in[3];
    const float* gamma = (const float*)d_in[4];
    const float* beta  = (const float*)d_in[5];
    const float* Wout  = (const float*)d_in[6];
    const float* bout  = (const float*)d_in[7];
    float* out = (float*)d_out;

    float *xproj, *H0, *H1, *red;
    unsigned* bar;
    cudaGetSymbolAddress((void**)&xproj, d_xproj);
    cudaGetSymbolAddress((void**)&H0,    d_H0);
    cudaGetSymbolAddress((void**)&H1,    d_H1);
    cudaGetSymbolAddress((void**)&red,   d_red);
    cudaGetSymbolAddress((void**)&bar,   d_bar);

    cudaFuncSetAttribute(lstm_rec, cudaFuncAttributeMaxDynamicSharedMemorySize, REC_BYTES);
    cudaFuncSetAttribute(gemm_bf16s, cudaFuncAttributeMaxDynamicSharedMemorySize, 65536);

    float* h_out = out + (size_t)B_ * T_ * V_;
    float* c_out = h_out + (size_t)L_ * B_ * S_;

    const size_t wstride = (size_t)GS_ * S_;

    init_bar_k<<<1, 1>>>(bar);

    // layer 0: xproj = gather(emb, x) @ Wx0^T
    gemm_bf16s<<<dim3(GS_ / 128, (T_ * B_) / 128), 256, 65536>>>(
        T_ * B_, GS_, S_, emb, x, Wx, nullptr, xproj, 0);
    lstm_rec<<<GRID_REC, 256, REC_BYTES>>>(
        xproj, Wh, gamma, beta, H0,
        h_out, c_out, red, bar);

    // layer 1: xproj = H0 @ Wx1^T
    gemm_bf16s<<<dim3(GS_ / 128, (T_ * B_) / 128), 256, 65536>>>(
        T_ * B_, GS_, S_, H0, nullptr, Wx + wstride, nullptr, xproj, 0);
    lstm_rec<<<GRID_REC, 256, REC_BYTES>>>(
        xproj, Wh + wstride, gamma + S_, beta + S_, H1,
        h_out + (size_t)B_ * S_, c_out + (size_t)B_ * S_, red, bar);

    // logits: out = H1 @ Wout^T + bout
    gemm_bf16s<<<dim3(V_ / 128, (T_ * B_) / 128), 256, 65536>>>(
        T_ * B_, V_, S_, H1, nullptr, Wout, bout, out, 1);
}

// round 4
// speedup vs baseline: 1.1106x; 1.0278x over previous
#include <cuda_runtime.h>
#include <cuda_bf16.h>
#include <math.h>

#define B_ 8
#define T_ 256
#define S_ 1024
#define V_ 32000
#define L_ 2
#define GS_ 4096
#define GRID_REC 128
#define EPS_ 1e-5f

// ---------------- static device scratch (no runtime allocation) ----------
__device__ float d_xproj[(size_t)T_ * B_ * GS_];            // [T][B][4S]
__device__ float d_H0[(size_t)T_ * B_ * S_];                // [T][B][S]
__device__ float d_H1[(size_t)T_ * B_ * S_];
__device__ float d_red[2 * B_ * GRID_REC * 2];              // LN partials, dbl-buffered
__device__ unsigned d_bar[2];                               // {count, generation}

__global__ void init_bar_k(unsigned* bar) { bar[0] = 0u; bar[1] = 0u; }

// =====================================================================
// bf16-split tensor-core GEMM: C[M,N] = A[M,K] @ B[N,K]^T (+bias)
// 3-term mma (AhBh + AhBl + AlBh), fp32 accum. Term-major mma ordering
// (no accumulator RAW back-to-back) + all fragment loads hoisted.
// =====================================================================

#define SWZ(r, w) ((w) ^ ((r) & 7) ^ (((r) >> 3) & 3))

__device__ __forceinline__ unsigned pack_hi(float x, float y, float& rx, float& ry) {
    __nv_bfloat16 bx = __float2bfloat16(x);
    __nv_bfloat16 by = __float2bfloat16(y);
    rx = x - __bfloat162float(bx);
    ry = y - __bfloat162float(by);
    __nv_bfloat162 p; p.x = bx; p.y = by;
    return *reinterpret_cast<unsigned*>(&p);
}
__device__ __forceinline__ unsigned pack_lo(float x, float y) {
    __nv_bfloat162 p; p.x = __float2bfloat16(x); p.y = __float2bfloat16(y);
    return *reinterpret_cast<unsigned*>(&p);
}

__device__ __forceinline__ void mma16816(float* c, const unsigned* a, const unsigned* b) {
    asm volatile(
        "mma.sync.aligned.m16n8k16.row.col.f32.bf16.bf16.f32 "
        "{%0,%1,%2,%3}, {%4,%5,%6,%7}, {%8,%9}, {%0,%1,%2,%3};\n"
        : "+f"(c[0]), "+f"(c[1]), "+f"(c[2]), "+f"(c[3])
        : "r"(a[0]), "r"(a[1]), "r"(a[2]), "r"(a[3]), "r"(b[0]), "r"(b[1]));
}

__device__ __forceinline__ void store_cvt(unsigned* sm, int stage, unsigned zh,
                                          int r, const float4* v) {
    unsigned base = (unsigned)stage * 8192u + zh;
    #pragma unroll
    for (int i = 0; i < 8; ++i) {
        int c = i >> 2;
        int wb = (i & 3) * 2;
        float lx0, ly0, lx1, ly1;
        unsigned h0 = pack_hi(v[i].x, v[i].y, lx0, ly0);
        unsigned h1 = pack_hi(v[i].z, v[i].w, lx1, ly1);
        unsigned l0 = pack_lo(lx0, ly0);
        unsigned l1 = pack_lo(lx1, ly1);
        unsigned rowoff = (unsigned)(c * 1024 + r * 8);
        sm[base + rowoff + SWZ(r, wb)]     = h0;
        sm[base + rowoff + SWZ(r, wb + 1)] = h1;
        sm[base + 2048u + rowoff + SWZ(r, wb)]     = l0;
        sm[base + 2048u + rowoff + SWZ(r, wb + 1)] = l1;
    }
}

__global__ void __launch_bounds__(256)
gemm_bf16s(int M, int N, int K,
           const float* __restrict__ A, const int* __restrict__ tok,
           const float* __restrict__ Bm, const float* __restrict__ bias,
           float* __restrict__ C, int mode)
{
    extern __shared__ unsigned sm[];          // 2 stages x 8192 words = 64KB
    const int tid = threadIdx.x;
    const int n0 = blockIdx.x * 128;
    const int m0 = blockIdx.y * 128;

    const int lr = tid & 127;
    const int isB = tid >> 7;
    const float* src;
    if (isB) {
        src = Bm + (size_t)(n0 + lr) * K;
    } else {
        int m = m0 + lr;
        if (tok) src = A + (size_t)__ldg(&tok[(m & 7) * T_ + (m >> 3)]) * K;
        else     src = A + (size_t)m * K;
    }
    const unsigned zh = isB ? 4096u : 0u;

    const int wid = tid >> 5, lane = tid & 31;
    const int warp_m = wid >> 2, warp_n = wid & 3;
    const int m_base = warp_m * 64, n_base = warp_n * 32;
    const int g = lane >> 2, q = lane & 3;

    float acc[4][4][4];
    #pragma unroll
    for (int i = 0; i < 4; ++i)
        #pragma unroll
        for (int j = 0; j < 4; ++j)
            #pragma unroll
            for (int k = 0; k < 4; ++k) acc[i][j][k] = 0.f;

    {
        float4 v[8];
        #pragma unroll
        for (int i = 0; i < 8; ++i) v[i] = __ldg((const float4*)src + i);
        store_cvt(sm, 0, zh, lr, v);
    }
    __syncthreads();

    const int KT = K >> 5;
    for (int kt = 0; kt < KT; ++kt) {
        const int cur = kt & 1;
        float4 v[8];
        const bool more = (kt + 1 < KT);
        if (more) {
            const float4* gsrc = (const float4*)(src + (size_t)(kt + 1) * 32);
            #pragma unroll
            for (int i = 0; i < 8; ++i) v[i] = __ldg(gsrc + i);
        }

        const unsigned* sA = sm + (unsigned)cur * 8192u;
        const unsigned* sB = sA + 4096u;

        #pragma unroll
        for (int c = 0; c < 2; ++c) {
            unsigned bh[4][2], bl[4][2], ah[4][4], al[4][4];
            #pragma unroll
            for (int fn = 0; fn < 4; ++fn) {
                int rn = n_base + fn * 8 + g;
                unsigned off = (unsigned)(c * 1024 + rn * 8);
                bh[fn][0] = sB[off + SWZ(rn, q)];
                bh[fn][1] = sB[off + SWZ(rn, q + 4)];
                bl[fn][0] = sB[2048u + off + SWZ(rn, q)];
                bl[fn][1] = sB[2048u + off + SWZ(rn, q + 4)];
            }
            #pragma unroll
            for (int fm = 0; fm < 4; ++fm) {
                int r0 = m_base + fm * 16 + g, r1 = r0 + 8;
                unsigned o0 = (unsigned)(c * 1024 + r0 * 8);
                unsigned o1 = (unsigned)(c * 1024 + r1 * 8);
                ah[fm][0] = sA[o0 + SWZ(r0, q)];
                ah[fm][1] = sA[o1 + SWZ(r1, q)];
                ah[fm][2] = sA[o0 + SWZ(r0, q + 4)];
                ah[fm][3] = sA[o1 + SWZ(r1, q + 4)];
                al[fm][0] = sA[2048u + o0 + SWZ(r0, q)];
                al[fm][1] = sA[2048u + o1 + SWZ(r1, q)];
                al[fm][2] = sA[2048u + o0 + SWZ(r0, q + 4)];
                al[fm][3] = sA[2048u + o1 + SWZ(r1, q + 4)];
            }
            // term-major: 16 independent accs between reuses of the same acc
            #pragma unroll
            for (int fm = 0; fm < 4; ++fm)
                #pragma unroll
                for (int fn = 0; fn < 4; ++fn)
                    mma16816(acc[fm][fn], ah[fm], bh[fn]);
            #pragma unroll
            for (int fm = 0; fm < 4; ++fm)
                #pragma unroll
                for (int fn = 0; fn < 4; ++fn)
                    mma16816(acc[fm][fn], ah[fm], bl[fn]);
            #pragma unroll
            for (int fm = 0; fm < 4; ++fm)
                #pragma unroll
                for (int fn = 0; fn < 4; ++fn)
                    mma16816(acc[fm][fn], al[fm], bh[fn]);
        }

        if (more) store_cvt(sm, cur ^ 1, zh, lr, v);
        __syncthreads();
    }

    #pragma unroll
    for (int fm = 0; fm < 4; ++fm) {
        int row0 = m0 + m_base + fm * 16 + g;
        int row1 = row0 + 8;
        float *p0, *p1;
        if (mode == 0) {
            p0 = C + (size_t)row0 * N;
            p1 = C + (size_t)row1 * N;
        } else {
            p0 = C + (size_t)(row0 & 7) * ((size_t)T_ * V_) + (size_t)(row0 >> 3) * V_;
            p1 = C + (size_t)(row1 & 7) * ((size_t)T_ * V_) + (size_t)(row1 >> 3) * V_;
        }
        #pragma unroll
        for (int fn = 0; fn < 4; ++fn) {
            int col = n0 + n_base + fn * 8 + q * 2;
            float b0 = 0.f, b1 = 0.f;
            if (bias) { b0 = __ldg(&bias[col]); b1 = __ldg(&bias[col + 1]); }
            float2 v0 = make_float2(acc[fm][fn][0] + b0, acc[fm][fn][1] + b1);
            float2 v1 = make_float2(acc[fm][fn][2] + b0, acc[fm][fn][3] + b1);
            *(float2*)(p0 + col) = v0;
            *(float2*)(p1 + col) = v1;
        }
    }
}

// ---------------- persistent recurrence: one layer, all T steps -----------
// f32x2 packed-FMA dot product, transposed pad-swizzled smem layouts.
// Wh_s[k][c] stride 36 (conflict-free LDS.128), h_s[k][b] stride 12.
#define WH_STRIDE 36
#define H_STRIDE  12
#define REC_FLOATS (1024*WH_STRIDE + 1024*H_STRIDE + 256 + 64 + 64 + 16 + 16 + 128)
#define REC_BYTES  (REC_FLOATS * 4)

__device__ __forceinline__ void grid_barrier(unsigned* bar) {
    __syncthreads();
    if (threadIdx.x == 0) {
        __threadfence();
        unsigned g = *((volatile unsigned*)&bar[1]);
        if (atomicAdd(&bar[0], 1u) == GRID_REC - 1) {
            bar[0] = 0u;
            __threadfence();
            atomicAdd(&bar[1], 1u);
        } else {
            while (*((volatile unsigned*)&bar[1]) == g) { }
        }
    }
    __syncthreads();
}

__device__ __forceinline__ float sigmf(float x) { return 1.f / (1.f + expf(-x)); }

__device__ __forceinline__ unsigned long long pk2(float x, float y) {
    unsigned long long d;
    asm("mov.b64 %0, {%1,%2};" : "=l"(d) : "f"(x), "f"(y));
    return d;
}
__device__ __forceinline__ void upk2(unsigned long long v, float& x, float& y) {
    asm("mov.b64 {%0,%1}, %2;" : "=f"(x), "=f"(y) : "l"(v));
}
__device__ __forceinline__ void fma2(unsigned long long& d, unsigned long long a,
                                     unsigned long long b) {
    asm("fma.rn.f32x2 %0, %1, %2, %0;" : "+l"(d) : "l"(a), "l"(b));
}

__global__ void __launch_bounds__(256, 1)
lstm_rec(const float* __restrict__ xproj,   // [T][B][4S]
         const float* __restrict__ Wh,      // [4S][S]
         const float* __restrict__ gamma, const float* __restrict__ beta,
         float* __restrict__ H,             // [T][B][S]
         float* __restrict__ hfin, float* __restrict__ cfin,  // [B][S] each
         float* __restrict__ red, unsigned* __restrict__ bar)
{
    extern __shared__ float smem[];
    float* Wh_s = smem;                        // 1024*36
    float* h_s  = Wh_s + 1024 * WH_STRIDE;     // 1024*12
    float* gbuf = h_s + 1024 * H_STRIDE;       // 32 cols x 8 b
    float* craw = gbuf + 256;                  // 64 ([u][b])
    float* hbuf = craw + 64;                   // 64
    float* gmb  = hbuf + 64;                   // gamma[8] | beta[8]
    float* stat = gmb + 16;                    // mu[8] | rstd[8]
    float* part = stat + 16;                   // 64 x 2

    const int tid = threadIdx.x;
    const int blk = blockIdx.x;
    const int s0  = blk * 8;

    {   // load Wh transposed: Wh_s[k*36 + c] = Wh[(g*S + s0+u)*S + k], c=g*8+u
        int c = tid & 31, kb = (tid >> 5) * 128;
        int g = c >> 3, u = c & 7;
        const float4* src = (const float4*)(Wh + (size_t)(g * S_ + s0 + u) * S_ + kb);
        #pragma unroll 4
        for (int j = 0; j < 32; ++j) {
            float4 v = __ldg(src + j);
            int k = kb + j * 4;
            Wh_s[(k + 0) * WH_STRIDE + c] = v.x;
            Wh_s[(k + 1) * WH_STRIDE + c] = v.y;
            Wh_s[(k + 2) * WH_STRIDE + c] = v.z;
            Wh_s[(k + 3) * WH_STRIDE + c] = v.w;
        }
    }
    if (tid < 8)  { gmb[tid] = __ldg(&gamma[s0 + tid]); gmb[8 + tid] = __ldg(&beta[s0 + tid]); }
    gbuf[tid] = 0.f;
    __syncthreads();

    const int w = tid >> 5, lane = tid & 31;
    const int cl0 = w * 4;
    const int uu = tid >> 3, bb = tid & 7;     // gate-thread coords (tid<64)

    float cprev = 0.f;                         // normalized cell, per (uu,bb)

    for (int t = 0; t < T_; ++t) {
        // prefetch xproj for this step
        float xpi = 0.f, xpf = 0.f, xpo = 0.f, xpg = 0.f;
        if (tid < 64) {
            const float* xp = xproj + (size_t)(t * B_ + bb) * GS_ + s0 + uu;
            xpi = __ldg(xp + 0 * S_); xpf = __ldg(xp + 1 * S_);
            xpo = __ldg(xp + 2 * S_); xpg = __ldg(xp + 3 * S_);
        }

        if (t > 0) {
            // ---- load h(t-1) transposed into regs (LDGs overlap LN finalize)
            const float* Hsrc = H + (size_t)(t - 1) * (B_ * S_);
            float hv[4][8];
            #pragma unroll
            for (int r = 0; r < 4; ++r)
                #pragma unroll
                for (int b = 0; b < 8; ++b)
                    hv[r][b] = __ldcg(Hsrc + b * S_ + tid + r * 256);

            // ---- LN finalize for step t-1 (reads red published at last barrier)
            {
                int par = (t - 1) & 1;
                const float* rp = red + (size_t)par * B_ * GRID_REC * 2;
                if (tid < 64) {
                    int b = tid >> 3, seg = tid & 7;
                    float s1 = 0.f, s2 = 0.f;
                    #pragma unroll
                    for (int q = 0; q < 16; ++q) {
                        float2 v = __ldcg((const float2*)(rp + ((size_t)b * GRID_REC + seg * 16 + q) * 2));
                        s1 += v.x; s2 += v.y;
                    }
                    part[tid * 2] = s1; part[tid * 2 + 1] = s2;
                }
            }
            __syncthreads();
            if (tid < 8) {
                float s1 = 0.f, s2 = 0.f;
                #pragma unroll
                for (int seg = 0; seg < 8; ++seg) {
                    s1 += part[(tid * 8 + seg) * 2];
                    s2 += part[(tid * 8 + seg) * 2 + 1];
                }
                float mu = s1 * (1.f / (float)S_);
                float var = s2 * (1.f / (float)S_) - mu * mu;
                stat[tid] = mu; stat[8 + tid] = rsqrtf(var + EPS_);
            }
            // store h to transposed smem rows k = tid + r*256
            #pragma unroll
            for (int r = 0; r < 4; ++r) {
                int k = tid + r * 256;
                *(float4*)(h_s + k * H_STRIDE)     = make_float4(hv[r][0], hv[r][1], hv[r][2], hv[r][3]);
                *(float4*)(h_s + k * H_STRIDE + 4) = make_float4(hv[r][4], hv[r][5], hv[r][6], hv[r][7]);
            }
            __syncthreads();

            if (tid < 64)   // normalize prev cell (register-resident)
                cprev = (craw[tid] - stat[bb]) * stat[8 + bb] * gmb[uu] + gmb[8 + uu];

            // ---- f32x2 dot: 4 gate cols x 8 batches per warp, split-K 32 lanes
            unsigned long long acc2[4][4];
            #pragma unroll
            for (int c = 0; c < 4; ++c)
                #pragma unroll
                for (int p = 0; p < 4; ++p) acc2[c][p] = 0ull;

            #pragma unroll 4
            for (int i = 0; i < 32; ++i) {
                int k = (i << 5) + lane;
                float4 wv = *(const float4*)(Wh_s + k * WH_STRIDE + cl0);
                float4 ha = *(const float4*)(h_s + k * H_STRIDE);
                float4 hb = *(const float4*)(h_s + k * H_STRIDE + 4);
                unsigned long long hp0 = pk2(ha.x, ha.y), hp1 = pk2(ha.z, ha.w);
                unsigned long long hp2 = pk2(hb.x, hb.y), hp3 = pk2(hb.z, hb.w);
                unsigned long long wp;
                wp = pk2(wv.x, wv.x);
                fma2(acc2[0][0], wp, hp0); fma2(acc2[0][1], wp, hp1);
                fma2(acc2[0][2], wp, hp2); fma2(acc2[0][3], wp, hp3);
                wp = pk2(wv.y, wv.y);
                fma2(acc2[1][0], wp, hp0); fma2(acc2[1][1], wp, hp1);
                fma2(acc2[1][2], wp, hp2); fma2(acc2[1][3], wp, hp3);
                wp = pk2(wv.z, wv.z);
                fma2(acc2[2][0], wp, hp0); fma2(acc2[2][1], wp, hp1);
                fma2(acc2[2][2], wp, hp2); fma2(acc2[2][3], wp, hp3);
                wp = pk2(wv.w, wv.w);
                fma2(acc2[3][0], wp, hp0); fma2(acc2[3][1], wp, hp1);
                fma2(acc2[3][2], wp, hp2); fma2(acc2[3][3], wp, hp3);
            }
            #pragma unroll
            for (int c = 0; c < 4; ++c)
                #pragma unroll
                for (int p = 0; p < 4; ++p) {
                    float lo, hi;
                    upk2(acc2[c][p], lo, hi);
                    #pragma unroll
                    for (int o = 16; o > 0; o >>= 1) {
                        lo += __shfl_xor_sync(0xffffffffu, lo, o);
                        hi += __shfl_xor_sync(0xffffffffu, hi, o);
                    }
                    if (lane == 0) {
                        gbuf[(cl0 + c) * 8 + 2 * p]     = lo;
                        gbuf[(cl0 + c) * 8 + 2 * p + 1] = hi;
                    }
                }
            __syncthreads();
        }

        if (tid < 64) {   // gates + cell/hidden update
            float pi = xpi + gbuf[(0 * 8 + uu) * 8 + bb];
            float pf = xpf + gbuf[(1 * 8 + uu) * 8 + bb];
            float po = xpo + gbuf[(2 * 8 + uu) * 8 + bb];
            float pg = xpg + gbuf[(3 * 8 + uu) * 8 + bb];
            float ig = sigmf(pi), fg = sigmf(pf), og = sigmf(po), gg = tanhf(pg);
            float cr = fg * cprev + ig * gg;
            float hh = og * tanhf(cr);
            craw[tid] = cr;
            hbuf[tid] = hh;
            H[(size_t)t * (B_ * S_) + bb * S_ + s0 + uu] = hh;
        }
        __syncthreads();

        if (tid < 8) {   // per-block LN partials for batch b=tid
            float s1 = 0.f, s2 = 0.f;
            #pragma unroll
            for (int u = 0; u < 8; ++u) { float v = craw[u * 8 + tid]; s1 += v; s2 += v * v; }
            float2* rp = (float2*)(red + ((size_t)(t & 1) * B_ + tid) * (GRID_REC * 2) + blk * 2);
            *rp = make_float2(s1, s2);
        }

        grid_barrier(bar);   // publishes H[t] + red
    }

    // final LN for t = T-1 -> cfin; hfin from hbuf
    {
        int par = (T_ - 1) & 1;
        const float* rp = red + (size_t)par * B_ * GRID_REC * 2;
        if (tid < 64) {
            int b = tid >> 3, seg = tid & 7;
            float s1 = 0.f, s2 = 0.f;
            #pragma unroll
            for (int q = 0; q < 16; ++q) {
                float2 v = __ldcg((const float2*)(rp + ((size_t)b * GRID_REC + seg * 16 + q) * 2));
                s1 += v.x; s2 += v.y;
            }
            part[tid * 2] = s1; part[tid * 2 + 1] = s2;
        }
        __syncthreads();
        if (tid < 8) {
            float s1 = 0.f, s2 = 0.f;
            #pragma unroll
            for (int seg = 0; seg < 8; ++seg) {
                s1 += part[(tid * 8 + seg) * 2];
                s2 += part[(tid * 8 + seg) * 2 + 1];
            }
            float mu = s1 * (1.f / (float)S_);
            float var = s2 * (1.f / (float)S_) - mu * mu;
            stat[tid] = mu; stat[8 + tid] = rsqrtf(var + EPS_);
        }
        __syncthreads();
        if (tid < 64) {
            float cn = (craw[tid] - stat[bb]) * stat[8 + bb] * gmb[uu] + gmb[8 + uu];
            cfin[bb * S_ + s0 + uu] = cn;
            hfin[bb * S_ + s0 + uu] = hbuf[tid];
        }
    }
}

// ---------------- host launcher -------------------------------------------
extern "C" void kernel_launch(void* const* d_in, const int* in_sizes, int n_in,
                              void* d_out, int out_size)
{
    (void)in_sizes; (void)n_in; (void)out_size;
    const int*   x     = (const int*)d_in[0];
    const float* emb   = (const float*)d_in[1];
    const float* Wx    = (const float*)d_in[2];
    const float* Wh    = (const float*)d_in[3];
    const float* gamma = (const float*)d_in[4];
    const float* beta  = (const float*)d_in[5];
    const float* Wout  = (const float*)d_in[6];
    const float* bout  = (const float*)d_in[7];
    float* out = (float*)d_out;

    float *xproj, *H0, *H1, *red;
    unsigned* bar;
    cudaGetSymbolAddress((void**)&xproj, d_xproj);
    cudaGetSymbolAddress((void**)&H0,    d_H0);
    cudaGetSymbolAddress((void**)&H1,    d_H1);
    cudaGetSymbolAddress((void**)&red,   d_red);
    cudaGetSymbolAddress((void**)&bar,   d_bar);

    cudaFuncSetAttribute(lstm_rec, cudaFuncAttributeMaxDynamicSharedMemorySize, REC_BYTES);
    cudaFuncSetAttribute(gemm_bf16s, cudaFuncAttributeMaxDynamicSharedMemorySize, 65536);

    float* h_out = out + (size_t)B_ * T_ * V_;
    float* c_out = h_out + (size_t)L_ * B_ * S_;

    const size_t wstride = (size_t)GS_ * S_;

    init_bar_k<<<1, 1>>>(bar);

    // layer 0: xproj = gather(emb, x) @ Wx0^T
    gemm_bf16s<<<dim3(GS_ / 128, (T_ * B_) / 128), 256, 65536>>>(
        T_ * B_, GS_, S_, emb, x, Wx, nullptr, xproj, 0);
    lstm_rec<<<GRID_REC, 256, REC_BYTES>>>(
        xproj, Wh, gamma, beta, H0,
        h_out, c_out, red, bar);

    // layer 1: xproj = H0 @ Wx1^T
    gemm_bf16s<<<dim3(GS_ / 128, (T_ * B_) / 128), 256, 65536>>>(
        T_ * B_, GS_, S_, H0, nullptr, Wx + wstride, nullptr, xproj, 0);
    lstm_rec<<<GRID_REC, 256, REC_BYTES>>>(
        xproj, Wh + wstride, gamma + S_, beta + S_, H1,
        h_out + (size_t)B_ * S_, c_out + (size_t)B_ * S_, red, bar);

    // logits: out = H1 @ Wout^T + bout
    gemm_bf16s<<<dim3(V_ / 128, (T_ * B_) / 128), 256, 65536>>>(
        T_ * B_, V_, S_, H1, nullptr, Wout, bout, out, 1);
}

// round 5
// speedup vs baseline: 1.2202x; 1.0987x over previous
#include <cuda_runtime.h>
#include <cuda_bf16.h>
#include <math.h>

#define B_ 8
#define T_ 256
#define S_ 1024
#define V_ 32000
#define L_ 2
#define GS_ 4096
#define GRID_REC 128
#define EPS_ 1e-5f

// ---------------- static device scratch (no runtime allocation) ----------
__device__ float d_xproj[(size_t)T_ * B_ * GS_];            // [T][B][4S]
__device__ float d_H0[(size_t)T_ * B_ * S_];                // [T][B][S]
__device__ float d_H1[(size_t)T_ * B_ * S_];
__device__ float d_red[2 * B_ * GRID_REC * 2];              // LN partials
__device__ unsigned d_bar[2];

// bf16 hi/lo split scratch
__device__ __nv_bfloat16 d_Wxh[(size_t)L_ * GS_ * S_];
__device__ __nv_bfloat16 d_Wxl[(size_t)L_ * GS_ * S_];
__device__ __nv_bfloat16 d_Wouth[(size_t)V_ * S_];
__device__ __nv_bfloat16 d_Woutl[(size_t)V_ * S_];
__device__ __nv_bfloat16 d_Ah[(size_t)T_ * B_ * S_];
__device__ __nv_bfloat16 d_Al[(size_t)T_ * B_ * S_];

__global__ void init_bar_k(unsigned* bar) { bar[0] = 0u; bar[1] = 0u; }

// ---------------- fp32 -> bf16 hi/lo split kernels -----------------------
__device__ __forceinline__ void split4(float4 v, unsigned& h0, unsigned& h1,
                                       unsigned& l0, unsigned& l1) {
    __nv_bfloat16 a = __float2bfloat16(v.x), b = __float2bfloat16(v.y);
    __nv_bfloat16 c = __float2bfloat16(v.z), d = __float2bfloat16(v.w);
    __nv_bfloat162 hA; hA.x = a; hA.y = b;
    __nv_bfloat162 hB; hB.x = c; hB.y = d;
    h0 = *reinterpret_cast<unsigned*>(&hA);
    h1 = *reinterpret_cast<unsigned*>(&hB);
    __nv_bfloat162 lA, lB;
    lA.x = __float2bfloat16(v.x - __bfloat162float(a));
    lA.y = __float2bfloat16(v.y - __bfloat162float(b));
    lB.x = __float2bfloat16(v.z - __bfloat162float(c));
    lB.y = __float2bfloat16(v.w - __bfloat162float(d));
    l0 = *reinterpret_cast<unsigned*>(&lA);
    l1 = *reinterpret_cast<unsigned*>(&lB);
}

__global__ void cvt_split_k(const float* __restrict__ s,
                            __nv_bfloat16* __restrict__ h,
                            __nv_bfloat16* __restrict__ l, int n4) {
    int i = blockIdx.x * blockDim.x + threadIdx.x;
    if (i >= n4) return;
    float4 v = __ldg((const float4*)s + i);
    uint2 hp, lp;
    split4(v, hp.x, hp.y, lp.x, lp.y);
    ((uint2*)h)[i] = hp;
    ((uint2*)l)[i] = lp;
}

// gather embedding rows (row r = t*8+b -> token x[b*T+t]) + split
__global__ void cvt_gather_k(const float* __restrict__ emb, const int* __restrict__ tok,
                             __nv_bfloat16* __restrict__ h, __nv_bfloat16* __restrict__ l) {
    int i = blockIdx.x * blockDim.x + threadIdx.x;   // over 2048*256 float4s
    int row = i >> 8, col4 = i & 255;
    int tk = __ldg(&tok[(row & 7) * T_ + (row >> 3)]);
    float4 v = __ldg((const float4*)(emb + (size_t)tk * S_) + col4);
    uint2 hp, lp;
    split4(v, hp.x, hp.y, lp.x, lp.y);
    ((uint2*)h)[i] = hp;
    ((uint2*)l)[i] = lp;
}

// =====================================================================
// bf16-split tensor-core GEMM, bf16 inputs pre-split in global.
// C[M,N] = (Ah+Al)[M,K] @ (Bh+Bl)[N,K]^T (+bias), 3-term mma, fp32 accum.
// Tile 128x128xK64, 8 warps (2x4), cp.async loads, ldmatrix fragments.
// grid.x = m-tiles (fast) for L2 reuse of B across m.
// mode 0: C row-major [M,N]; mode 1: logits row r=(t*8+b) -> out[b*T*V+t*V].
// =====================================================================

__device__ __forceinline__ void cpa16(unsigned dst, const void* src) {
    asm volatile("cp.async.cg.shared.global [%0], [%1], 16;\n" :: "r"(dst), "l"(src));
}
__device__ __forceinline__ void ldsm4(unsigned& r0, unsigned& r1, unsigned& r2,
                                      unsigned& r3, unsigned addr) {
    asm volatile("ldmatrix.sync.aligned.m8n8.x4.shared.b16 {%0,%1,%2,%3}, [%4];\n"
                 : "=r"(r0), "=r"(r1), "=r"(r2), "=r"(r3) : "r"(addr));
}
__device__ __forceinline__ void mma16816(float* c, const unsigned* a, const unsigned* b) {
    asm volatile(
        "mma.sync.aligned.m16n8k16.row.col.f32.bf16.bf16.f32 "
        "{%0,%1,%2,%3}, {%4,%5,%6,%7}, {%8,%9}, {%0,%1,%2,%3};\n"
        : "+f"(c[0]), "+f"(c[1]), "+f"(c[2]), "+f"(c[3])
        : "r"(a[0]), "r"(a[1]), "r"(a[2]), "r"(a[3]), "r"(b[0]), "r"(b[1]));
}

#define GEMM_SMEM 131072

__global__ void __launch_bounds__(256)
gemm_tc(int M, int N, int K,
        const __nv_bfloat16* __restrict__ Ah, const __nv_bfloat16* __restrict__ Al,
        const __nv_bfloat16* __restrict__ Bh, const __nv_bfloat16* __restrict__ Bl,
        const float* __restrict__ bias, float* __restrict__ C, int mode)
{
    extern __shared__ char smx[];
    const unsigned sbase = (unsigned)__cvta_generic_to_shared(smx);
    const int tid = threadIdx.x;
    const int m0 = blockIdx.x * 128;
    const int n0 = blockIdx.y * 128;

    // ---- loader role: one row per thread, hi+lo ----
    const int lr = tid & 127;
    const int isB = tid >> 7;
    const __nv_bfloat16* gh = isB ? (Bh + (size_t)(n0 + lr) * K)
                                  : (Ah + (size_t)(m0 + lr) * K);
    const __nv_bfloat16* gl = isB ? (Bl + (size_t)(n0 + lr) * K)
                                  : (Al + (size_t)(m0 + lr) * K);
    const unsigned matH = isB ? 32768u : 0u;        // byte offsets within stage
    const unsigned matL = matH + 16384u;
    const unsigned dstRow = (unsigned)lr * 128u;
    const unsigned swL = (unsigned)(lr & 7) * 16u;  // byte-chunk swizzle

    // ---- compute role coords ----
    const int wid = tid >> 5, lane = tid & 31;
    const int warp_m = wid >> 2, warp_n = wid & 3;
    const int m_base = warp_m * 64, n_base = warp_n * 32;
    const unsigned aswz = (unsigned)(lane & 7) * 16u;
    const unsigned arow = (unsigned)(m_base + (lane & 7) + ((lane >> 3) & 1) * 8);
    const unsigned acol = (unsigned)(lane >> 4);           // 0/1
    const unsigned brow = (unsigned)(n_base + (lane & 7) + ((lane >> 4) & 1) * 8);
    const unsigned bcol = (unsigned)((lane >> 3) & 1);     // 0/1

    float acc[4][4][4];
    #pragma unroll
    for (int i = 0; i < 4; ++i)
        #pragma unroll
        for (int j = 0; j < 4; ++j)
            #pragma unroll
            for (int k = 0; k < 4; ++k) acc[i][j][k] = 0.f;

    const int KT = K >> 6;   // K64 steps

    // prologue: stage 0
    {
        unsigned sb = sbase + dstRow;
        #pragma unroll
        for (int c = 0; c < 8; ++c) {
            unsigned off = ((unsigned)(c * 16)) ^ swL;
            cpa16(sb + matH + off, gh + c * 8);
            cpa16(sb + matL + off, gl + c * 8);
        }
        asm volatile("cp.async.commit_group;\n");
    }

    for (int kt = 0; kt < KT; ++kt) {
        const int cur = kt & 1;
        const bool more = (kt + 1 < KT);
        if (more) {
            unsigned sb = sbase + (unsigned)(cur ^ 1) * 65536u + dstRow;
            const __nv_bfloat16* ph = gh + (kt + 1) * 64;
            const __nv_bfloat16* pl = gl + (kt + 1) * 64;
            #pragma unroll
            for (int c = 0; c < 8; ++c) {
                unsigned off = ((unsigned)(c * 16)) ^ swL;
                cpa16(sb + matH + off, ph + c * 8);
                cpa16(sb + matL + off, pl + c * 8);
            }
            asm volatile("cp.async.commit_group;\n");
            asm volatile("cp.async.wait_group 1;\n");
        } else {
            asm volatile("cp.async.wait_group 0;\n");
        }
        __syncthreads();

        const unsigned sb = sbase + (unsigned)cur * 65536u;

        #pragma unroll
        for (int kc = 0; kc < 4; ++kc) {
            unsigned ah[4][4], al[4][4], bh[4][2], bl[4][2];
            const unsigned ac = ((2u * kc + acol) * 16u) ^ aswz;
            const unsigned bc = ((2u * kc + bcol) * 16u) ^ aswz;
            #pragma unroll
            for (int p = 0; p < 2; ++p) {
                unsigned addr = sb + 32768u + (brow + p * 16u) * 128u + bc;
                ldsm4(bh[2*p][0], bh[2*p][1], bh[2*p+1][0], bh[2*p+1][1], addr);
                ldsm4(bl[2*p][0], bl[2*p][1], bl[2*p+1][0], bl[2*p+1][1], addr + 16384u);
            }
            #pragma unroll
            for (int fm = 0; fm < 4; ++fm) {
                unsigned addr = sb + (arow + fm * 16u) * 128u + ac;
                ldsm4(ah[fm][0], ah[fm][1], ah[fm][2], ah[fm][3], addr);
                ldsm4(al[fm][0], al[fm][1], al[fm][2], al[fm][3], addr + 16384u);
            }
            #pragma unroll
            for (int fm = 0; fm < 4; ++fm)
                #pragma unroll
                for (int fn = 0; fn < 4; ++fn)
                    mma16816(acc[fm][fn], ah[fm], bh[fn]);
            #pragma unroll
            for (int fm = 0; fm < 4; ++fm)
                #pragma unroll
                for (int fn = 0; fn < 4; ++fn)
                    mma16816(acc[fm][fn], ah[fm], bl[fn]);
            #pragma unroll
            for (int fm = 0; fm < 4; ++fm)
                #pragma unroll
                for (int fn = 0; fn < 4; ++fn)
                    mma16816(acc[fm][fn], al[fm], bh[fn]);
        }
        __syncthreads();
    }

    // ---- epilogue ----
    const int g = lane >> 2, q = lane & 3;
    #pragma unroll
    for (int fm = 0; fm < 4; ++fm) {
        int row0 = m0 + m_base + fm * 16 + g;
        int row1 = row0 + 8;
        float *p0, *p1;
        if (mode == 0) {
            p0 = C + (size_t)row0 * N;
            p1 = C + (size_t)row1 * N;
        } else {
            p0 = C + (size_t)(row0 & 7) * ((size_t)T_ * V_) + (size_t)(row0 >> 3) * V_;
            p1 = C + (size_t)(row1 & 7) * ((size_t)T_ * V_) + (size_t)(row1 >> 3) * V_;
        }
        #pragma unroll
        for (int fn = 0; fn < 4; ++fn) {
            int col = n0 + n_base + fn * 8 + q * 2;
            float b0 = 0.f, b1 = 0.f;
            if (bias) { b0 = __ldg(&bias[col]); b1 = __ldg(&bias[col + 1]); }
            float2 v0 = make_float2(acc[fm][fn][0] + b0, acc[fm][fn][1] + b1);
            float2 v1 = make_float2(acc[fm][fn][2] + b0, acc[fm][fn][3] + b1);
            *(float2*)(p0 + col) = v0;
            *(float2*)(p1 + col) = v1;
        }
    }
}

// ---------------- persistent recurrence (unchanged from round 4) ----------
#define WH_STRIDE 36
#define H_STRIDE  12
#define REC_FLOATS (1024*WH_STRIDE + 1024*H_STRIDE + 256 + 64 + 64 + 16 + 16 + 128)
#define REC_BYTES  (REC_FLOATS * 4)

__device__ __forceinline__ void grid_barrier(unsigned* bar) {
    __syncthreads();
    if (threadIdx.x == 0) {
        __threadfence();
        unsigned g = *((volatile unsigned*)&bar[1]);
        if (atomicAdd(&bar[0], 1u) == GRID_REC - 1) {
            bar[0] = 0u;
            __threadfence();
            atomicAdd(&bar[1], 1u);
        } else {
            while (*((volatile unsigned*)&bar[1]) == g) { }
        }
    }
    __syncthreads();
}

__device__ __forceinline__ float sigmf(float x) { return 1.f / (1.f + expf(-x)); }

__device__ __forceinline__ unsigned long long pk2(float x, float y) {
    unsigned long long d;
    asm("mov.b64 %0, {%1,%2};" : "=l"(d) : "f"(x), "f"(y));
    return d;
}
__device__ __forceinline__ void upk2(unsigned long long v, float& x, float& y) {
    asm("mov.b64 {%0,%1}, %2;" : "=f"(x), "=f"(y) : "l"(v));
}
__device__ __forceinline__ void fma2(unsigned long long& d, unsigned long long a,
                                     unsigned long long b) {
    asm("fma.rn.f32x2 %0, %1, %2, %0;" : "+l"(d) : "l"(a), "l"(b));
}

__global__ void __launch_bounds__(256, 1)
lstm_rec(const float* __restrict__ xproj,
         const float* __restrict__ Wh,
         const float* __restrict__ gamma, const float* __restrict__ beta,
         float* __restrict__ H,
         float* __restrict__ hfin, float* __restrict__ cfin,
         float* __restrict__ red, unsigned* __restrict__ bar)
{
    extern __shared__ float smem[];
    float* Wh_s = smem;
    float* h_s  = Wh_s + 1024 * WH_STRIDE;
    float* gbuf = h_s + 1024 * H_STRIDE;
    float* craw = gbuf + 256;
    float* hbuf = craw + 64;
    float* gmb  = hbuf + 64;
    float* stat = gmb + 16;
    float* part = stat + 16;

    const int tid = threadIdx.x;
    const int blk = blockIdx.x;
    const int s0  = blk * 8;

    {
        int c = tid & 31, kb = (tid >> 5) * 128;
        int g = c >> 3, u = c & 7;
        const float4* src = (const float4*)(Wh + (size_t)(g * S_ + s0 + u) * S_ + kb);
        #pragma unroll 4
        for (int j = 0; j < 32; ++j) {
            float4 v = __ldg(src + j);
            int k = kb + j * 4;
            Wh_s[(k + 0) * WH_STRIDE + c] = v.x;
            Wh_s[(k + 1) * WH_STRIDE + c] = v.y;
            Wh_s[(k + 2) * WH_STRIDE + c] = v.z;
            Wh_s[(k + 3) * WH_STRIDE + c] = v.w;
        }
    }
    if (tid < 8)  { gmb[tid] = __ldg(&gamma[s0 + tid]); gmb[8 + tid] = __ldg(&beta[s0 + tid]); }
    gbuf[tid] = 0.f;
    __syncthreads();

    const int w = tid >> 5, lane = tid & 31;
    const int cl0 = w * 4;
    const int uu = tid >> 3, bb = tid & 7;

    float cprev = 0.f;

    for (int t = 0; t < T_; ++t) {
        float xpi = 0.f, xpf = 0.f, xpo = 0.f, xpg = 0.f;
        if (tid < 64) {
            const float* xp = xproj + (size_t)(t * B_ + bb) * GS_ + s0 + uu;
            xpi = __ldg(xp + 0 * S_); xpf = __ldg(xp + 1 * S_);
            xpo = __ldg(xp + 2 * S_); xpg = __ldg(xp + 3 * S_);
        }

        if (t > 0) {
            const float* Hsrc = H + (size_t)(t - 1) * (B_ * S_);
            float hv[4][8];
            #pragma unroll
            for (int r = 0; r < 4; ++r)
                #pragma unroll
                for (int b = 0; b < 8; ++b)
                    hv[r][b] = __ldcg(Hsrc + b * S_ + tid + r * 256);

            {
                int par = (t - 1) & 1;
                const float* rp = red + (size_t)par * B_ * GRID_REC * 2;
                if (tid < 64) {
                    int b = tid >> 3, seg = tid & 7;
                    float s1 = 0.f, s2 = 0.f;
                    #pragma unroll
                    for (int q = 0; q < 16; ++q) {
                        float2 v = __ldcg((const float2*)(rp + ((size_t)b * GRID_REC + seg * 16 + q) * 2));
                        s1 += v.x; s2 += v.y;
                    }
                    part[tid * 2] = s1; part[tid * 2 + 1] = s2;
                }
            }
            __syncthreads();
            if (tid < 8) {
                float s1 = 0.f, s2 = 0.f;
                #pragma unroll
                for (int seg = 0; seg < 8; ++seg) {
                    s1 += part[(tid * 8 + seg) * 2];
                    s2 += part[(tid * 8 + seg) * 2 + 1];
                }
                float mu = s1 * (1.f / (float)S_);
                float var = s2 * (1.f / (float)S_) - mu * mu;
                stat[tid] = mu; stat[8 + tid] = rsqrtf(var + EPS_);
            }
            #pragma unroll
            for (int r = 0; r < 4; ++r) {
                int k = tid + r * 256;
                *(float4*)(h_s + k * H_STRIDE)     = make_float4(hv[r][0], hv[r][1], hv[r][2], hv[r][3]);
                *(float4*)(h_s + k * H_STRIDE + 4) = make_float4(hv[r][4], hv[r][5], hv[r][6], hv[r][7]);
            }
            __syncthreads();

            if (tid < 64)
                cprev = (craw[tid] - stat[bb]) * stat[8 + bb] * gmb[uu] + gmb[8 + uu];

            unsigned long long acc2[4][4];
            #pragma unroll
            for (int c = 0; c < 4; ++c)
                #pragma unroll
                for (int p = 0; p < 4; ++p) acc2[c][p] = 0ull;

            #pragma unroll 4
            for (int i = 0; i < 32; ++i) {
                int k = (i << 5) + lane;
                float4 wv = *(const float4*)(Wh_s + k * WH_STRIDE + cl0);
                float4 ha = *(const float4*)(h_s + k * H_STRIDE);
                float4 hb = *(const float4*)(h_s + k * H_STRIDE + 4);
                unsigned long long hp0 = pk2(ha.x, ha.y), hp1 = pk2(ha.z, ha.w);
                unsigned long long hp2 = pk2(hb.x, hb.y), hp3 = pk2(hb.z, hb.w);
                unsigned long long wp;
                wp = pk2(wv.x, wv.x);
                fma2(acc2[0][0], wp, hp0); fma2(acc2[0][1], wp, hp1);
                fma2(acc2[0][2], wp, hp2); fma2(acc2[0][3], wp, hp3);
                wp = pk2(wv.y, wv.y);
                fma2(acc2[1][0], wp, hp0); fma2(acc2[1][1], wp, hp1);
                fma2(acc2[1][2], wp, hp2); fma2(acc2[1][3], wp, hp3);
                wp = pk2(wv.z, wv.z);
                fma2(acc2[2][0], wp, hp0); fma2(acc2[2][1], wp, hp1);
                fma2(acc2[2][2], wp, hp2); fma2(acc2[2][3], wp, hp3);
                wp = pk2(wv.w, wv.w);
                fma2(acc2[3][0], wp, hp0); fma2(acc2[3][1], wp, hp1);
                fma2(acc2[3][2], wp, hp2); fma2(acc2[3][3], wp, hp3);
            }
            #pragma unroll
            for (int c = 0; c < 4; ++c)
                #pragma unroll
                for (int p = 0; p < 4; ++p) {
                    float lo, hi;
                    upk2(acc2[c][p], lo, hi);
                    #pragma unroll
                    for (int o = 16; o > 0; o >>= 1) {
                        lo += __shfl_xor_sync(0xffffffffu, lo, o);
                        hi += __shfl_xor_sync(0xffffffffu, hi, o);
                    }
                    if (lane == 0) {
                        gbuf[(cl0 + c) * 8 + 2 * p]     = lo;
                        gbuf[(cl0 + c) * 8 + 2 * p + 1] = hi;
                    }
                }
            __syncthreads();
        }

        if (tid < 64) {
            float pi = xpi + gbuf[(0 * 8 + uu) * 8 + bb];
            float pf = xpf + gbuf[(1 * 8 + uu) * 8 + bb];
            float po = xpo + gbuf[(2 * 8 + uu) * 8 + bb];
            float pg = xpg + gbuf[(3 * 8 + uu) * 8 + bb];
            float ig = sigmf(pi), fg = sigmf(pf), og = sigmf(po), gg = tanhf(pg);
            float cr = fg * cprev + ig * gg;
            float hh = og * tanhf(cr);
            craw[tid] = cr;
            hbuf[tid] = hh;
            H[(size_t)t * (B_ * S_) + bb * S_ + s0 + uu] = hh;
        }
        __syncthreads();

        if (tid < 8) {
            float s1 = 0.f, s2 = 0.f;
            #pragma unroll
            for (int u = 0; u < 8; ++u) { float v = craw[u * 8 + tid]; s1 += v; s2 += v * v; }
            float2* rp = (float2*)(red + ((size_t)(t & 1) * B_ + tid) * (GRID_REC * 2) + blk * 2);
            *rp = make_float2(s1, s2);
        }

        grid_barrier(bar);
    }

    {
        int par = (T_ - 1) & 1;
        const float* rp = red + (size_t)par * B_ * GRID_REC * 2;
        if (tid < 64) {
            int b = tid >> 3, seg = tid & 7;
            float s1 = 0.f, s2 = 0.f;
            #pragma unroll
            for (int q = 0; q < 16; ++q) {
                float2 v = __ldcg((const float2*)(rp + ((size_t)b * GRID_REC + seg * 16 + q) * 2));
                s1 += v.x; s2 += v.y;
            }
            part[tid * 2] = s1; part[tid * 2 + 1] = s2;
        }
        __syncthreads();
        if (tid < 8) {
            float s1 = 0.f, s2 = 0.f;
            #pragma unroll
            for (int seg = 0; seg < 8; ++seg) {
                s1 += part[(tid * 8 + seg) * 2];
                s2 += part[(tid * 8 + seg) * 2 + 1];
            }
            float mu = s1 * (1.f / (float)S_);
            float var = s2 * (1.f / (float)S_) - mu * mu;
            stat[tid] = mu; stat[8 + tid] = rsqrtf(var + EPS_);
        }
        __syncthreads();
        if (tid < 64) {
            float cn = (craw[tid] - stat[bb]) * stat[8 + bb] * gmb[uu] + gmb[8 + uu];
            cfin[bb * S_ + s0 + uu] = cn;
            hfin[bb * S_ + s0 + uu] = hbuf[tid];
        }
    }
}

// ---------------- host launcher -------------------------------------------
extern "C" void kernel_launch(void* const* d_in, const int* in_sizes, int n_in,
                              void* d_out, int out_size)
{
    (void)in_sizes; (void)n_in; (void)out_size;
    const int*   x     = (const int*)d_in[0];
    const float* emb   = (const float*)d_in[1];
    const float* Wx    = (const float*)d_in[2];
    const float* Wh    = (const float*)d_in[3];
    const float* gamma = (const float*)d_in[4];
    const float* beta  = (const float*)d_in[5];
    const float* Wout  = (const float*)d_in[6];
    const float* bout  = (const float*)d_in[7];
    float* out = (float*)d_out;

    float *xproj, *H0, *H1, *red;
    unsigned* bar;
    __nv_bfloat16 *Wxh, *Wxl, *Wouth, *Woutl, *Ah, *Al;
    cudaGetSymbolAddress((void**)&xproj, d_xproj);
    cudaGetSymbolAddress((void**)&H0,    d_H0);
    cudaGetSymbolAddress((void**)&H1,    d_H1);
    cudaGetSymbolAddress((void**)&red,   d_red);
    cudaGetSymbolAddress((void**)&bar,   d_bar);
    cudaGetSymbolAddress((void**)&Wxh,   d_Wxh);
    cudaGetSymbolAddress((void**)&Wxl,   d_Wxl);
    cudaGetSymbolAddress((void**)&Wouth, d_Wouth);
    cudaGetSymbolAddress((void**)&Woutl, d_Woutl);
    cudaGetSymbolAddress((void**)&Ah,    d_Ah);
    cudaGetSymbolAddress((void**)&Al,    d_Al);

    cudaFuncSetAttribute(lstm_rec, cudaFuncAttributeMaxDynamicSharedMemorySize, REC_BYTES);
    cudaFuncSetAttribute(gemm_tc, cudaFuncAttributeMaxDynamicSharedMemorySize, GEMM_SMEM);

    float* h_out = out + (size_t)B_ * T_ * V_;
    float* c_out = h_out + (size_t)L_ * B_ * S_;

    const size_t wstride = (size_t)GS_ * S_;
    const size_t wstride_bf = (size_t)GS_ * S_;

    init_bar_k<<<1, 1>>>(bar);

    // pre-split weights
    cvt_split_k<<<(L_ * GS_ * S_ / 4 + 255) / 256, 256>>>(Wx, Wxh, Wxl, L_ * GS_ * S_ / 4);
    cvt_split_k<<<(V_ * S_ / 4 + 255) / 256, 256>>>(Wout, Wouth, Woutl, V_ * S_ / 4);

    // layer 0: A = gathered+split emb rows; xproj = A @ Wx0^T
    cvt_gather_k<<<(T_ * B_ * S_ / 4 + 255) / 256, 256>>>(emb, x, Ah, Al);
    gemm_tc<<<dim3((T_ * B_) / 128, GS_ / 128), 256, GEMM_SMEM>>>(
        T_ * B_, GS_, S_, Ah, Al, Wxh, Wxl, nullptr, xproj, 0);
    lstm_rec<<<GRID_REC, 256, REC_BYTES>>>(
        xproj, Wh, gamma, beta, H0, h_out, c_out, red, bar);

    // layer 1: A = split(H0); xproj = A @ Wx1^T
    cvt_split_k<<<(T_ * B_ * S_ / 4 + 255) / 256, 256>>>(H0, Ah, Al, T_ * B_ * S_ / 4);
    gemm_tc<<<dim3((T_ * B_) / 128, GS_ / 128), 256, GEMM_SMEM>>>(
        T_ * B_, GS_, S_, Ah, Al, Wxh + wstride_bf, Wxl + wstride_bf, nullptr, xproj, 0);
    lstm_rec<<<GRID_REC, 256, REC_BYTES>>>(
        xproj, Wh + wstride, gamma + S_, beta + S_, H1,
        h_out + (size_t)B_ * S_, c_out + (size_t)B_ * S_, red, bar);

    // logits: out = H1 @ Wout^T + bout
    cvt_split_k<<<(T_ * B_ * S_ / 4 + 255) / 256, 256>>>(H1, Ah, Al, T_ * B_ * S_ / 4);
    gemm_tc<<<dim3((T_ * B_) / 128, V_ / 128), 256, GEMM_SMEM>>>(
        T_ * B_, V_, S_, Ah, Al, Wouth, Woutl, bout, out, 1);
}

// round 6
// speedup vs baseline: 1.2493x; 1.0239x over previous
#include <cuda_runtime.h>
#include <cuda_bf16.h>
#include <math.h>

#define B_ 8
#define T_ 256
#define S_ 1024
#define V_ 32000
#define L_ 2
#define GS_ 4096
#define GRID_REC 128
#define EPS_ 1e-5f

// ---------------- static device scratch (no runtime allocation) ----------
__device__ float d_xproj[(size_t)T_ * B_ * GS_];            // [T][B][4S]
__device__ float d_H0[(size_t)T_ * B_ * S_];                // [T][B][S]
__device__ float d_H1[(size_t)T_ * B_ * S_];
__device__ float d_red[2 * B_ * GRID_REC * 2];              // LN partials
__device__ unsigned d_bar[64];                              // [0]=count, [32]=gen (separate 128B lines)

// bf16 hi/lo split scratch
__device__ __nv_bfloat16 d_Wxh[(size_t)L_ * GS_ * S_];
__device__ __nv_bfloat16 d_Wxl[(size_t)L_ * GS_ * S_];
__device__ __nv_bfloat16 d_Wouth[(size_t)V_ * S_];
__device__ __nv_bfloat16 d_Woutl[(size_t)V_ * S_];
__device__ __nv_bfloat16 d_Ah[(size_t)T_ * B_ * S_];
__device__ __nv_bfloat16 d_Al[(size_t)T_ * B_ * S_];

__global__ void init_bar_k(unsigned* bar) { bar[0] = 0u; bar[32] = 0u; }

// ---------------- fp32 -> bf16 hi/lo split kernels -----------------------
__device__ __forceinline__ void split4(float4 v, unsigned& h0, unsigned& h1,
                                       unsigned& l0, unsigned& l1) {
    __nv_bfloat16 a = __float2bfloat16(v.x), b = __float2bfloat16(v.y);
    __nv_bfloat16 c = __float2bfloat16(v.z), d = __float2bfloat16(v.w);
    __nv_bfloat162 hA; hA.x = a; hA.y = b;
    __nv_bfloat162 hB; hB.x = c; hB.y = d;
    h0 = *reinterpret_cast<unsigned*>(&hA);
    h1 = *reinterpret_cast<unsigned*>(&hB);
    __nv_bfloat162 lA, lB;
    lA.x = __float2bfloat16(v.x - __bfloat162float(a));
    lA.y = __float2bfloat16(v.y - __bfloat162float(b));
    lB.x = __float2bfloat16(v.z - __bfloat162float(c));
    lB.y = __float2bfloat16(v.w - __bfloat162float(d));
    l0 = *reinterpret_cast<unsigned*>(&lA);
    l1 = *reinterpret_cast<unsigned*>(&lB);
}

__global__ void cvt_split_k(const float* __restrict__ s,
                            __nv_bfloat16* __restrict__ h,
                            __nv_bfloat16* __restrict__ l, int n4) {
    int i = blockIdx.x * blockDim.x + threadIdx.x;
    if (i >= n4) return;
    float4 v = __ldg((const float4*)s + i);
    uint2 hp, lp;
    split4(v, hp.x, hp.y, lp.x, lp.y);
    ((uint2*)h)[i] = hp;
    ((uint2*)l)[i] = lp;
}

// gather embedding rows (row r = t*8+b -> token x[b*T+t]) + split
__global__ void cvt_gather_k(const float* __restrict__ emb, const int* __restrict__ tok,
                             __nv_bfloat16* __restrict__ h, __nv_bfloat16* __restrict__ l) {
    int i = blockIdx.x * blockDim.x + threadIdx.x;   // over 2048*256 float4s
    int row = i >> 8, col4 = i & 255;
    int tk = __ldg(&tok[(row & 7) * T_ + (row >> 3)]);
    float4 v = __ldg((const float4*)(emb + (size_t)tk * S_) + col4);
    uint2 hp, lp;
    split4(v, hp.x, hp.y, lp.x, lp.y);
    ((uint2*)h)[i] = hp;
    ((uint2*)l)[i] = lp;
}

// =====================================================================
// bf16-split tensor-core GEMM, bf16 inputs pre-split in global.
// C[M,N] = (Ah+Al)[M,K] @ (Bh+Bl)[N,K]^T (+bias), 3-term mma, fp32 accum.
// Tile 128x128xK64, 8 warps (2x4), cp.async, ldmatrix, 3-stage pipeline,
// one __syncthreads per K-iter.
// =====================================================================

__device__ __forceinline__ void cpa16(unsigned dst, const void* src) {
    asm volatile("cp.async.cg.shared.global [%0], [%1], 16;\n" :: "r"(dst), "l"(src));
}
__device__ __forceinline__ void ldsm4(unsigned& r0, unsigned& r1, unsigned& r2,
                                      unsigned& r3, unsigned addr) {
    asm volatile("ldmatrix.sync.aligned.m8n8.x4.shared.b16 {%0,%1,%2,%3}, [%4];\n"
                 : "=r"(r0), "=r"(r1), "=r"(r2), "=r"(r3) : "r"(addr));
}
__device__ __forceinline__ void mma16816(float* c, const unsigned* a, const unsigned* b) {
    asm volatile(
        "mma.sync.aligned.m16n8k16.row.col.f32.bf16.bf16.f32 "
        "{%0,%1,%2,%3}, {%4,%5,%6,%7}, {%8,%9}, {%0,%1,%2,%3};\n"
        : "+f"(c[0]), "+f"(c[1]), "+f"(c[2]), "+f"(c[3])
        : "r"(a[0]), "r"(a[1]), "r"(a[2]), "r"(a[3]), "r"(b[0]), "r"(b[1]));
}

#define STAGE_BYTES 65536u
#define GEMM_SMEM   (3 * 65536)

__global__ void __launch_bounds__(256)
gemm_tc(int M, int N, int K,
        const __nv_bfloat16* __restrict__ Ah, const __nv_bfloat16* __restrict__ Al,
        const __nv_bfloat16* __restrict__ Bh, const __nv_bfloat16* __restrict__ Bl,
        const float* __restrict__ bias, float* __restrict__ C, int mode)
{
    extern __shared__ char smx[];
    const unsigned sbase = (unsigned)__cvta_generic_to_shared(smx);
    const int tid = threadIdx.x;
    const int m0 = blockIdx.x * 128;
    const int n0 = blockIdx.y * 128;

    // ---- loader role: one row per thread, hi+lo ----
    const int lr = tid & 127;
    const int isB = tid >> 7;
    const __nv_bfloat16* gh = isB ? (Bh + (size_t)(n0 + lr) * K)
                                  : (Ah + (size_t)(m0 + lr) * K);
    const __nv_bfloat16* gl = isB ? (Bl + (size_t)(n0 + lr) * K)
                                  : (Al + (size_t)(m0 + lr) * K);
    const unsigned matH = isB ? 32768u : 0u;
    const unsigned matL = matH + 16384u;
    const unsigned dstRow = (unsigned)lr * 128u;
    const unsigned swL = (unsigned)(lr & 7) * 16u;

    // ---- compute role coords ----
    const int wid = tid >> 5, lane = tid & 31;
    const int warp_m = wid >> 2, warp_n = wid & 3;
    const int m_base = warp_m * 64, n_base = warp_n * 32;
    const unsigned aswz = (unsigned)(lane & 7) * 16u;
    const unsigned arow = (unsigned)(m_base + (lane & 7) + ((lane >> 3) & 1) * 8);
    const unsigned acol = (unsigned)(lane >> 4);
    const unsigned brow = (unsigned)(n_base + (lane & 7) + ((lane >> 4) & 1) * 8);
    const unsigned bcol = (unsigned)((lane >> 3) & 1);

    float acc[4][4][4];
    #pragma unroll
    for (int i = 0; i < 4; ++i)
        #pragma unroll
        for (int j = 0; j < 4; ++j)
            #pragma unroll
            for (int k = 0; k < 4; ++k) acc[i][j][k] = 0.f;

    const int KT = K >> 6;   // K64 steps (>= 2 for all our shapes)

    // prologue: stages 0 and 1
    #pragma unroll
    for (int s = 0; s < 2; ++s) {
        unsigned sb = sbase + (unsigned)s * STAGE_BYTES + dstRow;
        const __nv_bfloat16* ph = gh + s * 64;
        const __nv_bfloat16* pl = gl + s * 64;
        #pragma unroll
        for (int c = 0; c < 8; ++c) {
            unsigned off = ((unsigned)(c * 16)) ^ swL;
            cpa16(sb + matH + off, ph + c * 8);
            cpa16(sb + matL + off, pl + c * 8);
        }
        asm volatile("cp.async.commit_group;\n");
    }

    int cur = 0;
    for (int kt = 0; kt < KT; ++kt) {
        if (kt < KT - 1) asm volatile("cp.async.wait_group 1;\n");
        else             asm volatile("cp.async.wait_group 0;\n");
        __syncthreads();

        const unsigned sb = sbase + (unsigned)cur * STAGE_BYTES;

        #pragma unroll
        for (int kc = 0; kc < 4; ++kc) {
            unsigned ah[4][4], al[4][4], bh[4][2], bl[4][2];
            const unsigned ac = ((2u * kc + acol) * 16u) ^ aswz;
            const unsigned bc = ((2u * kc + bcol) * 16u) ^ aswz;
            #pragma unroll
            for (int p = 0; p < 2; ++p) {
                unsigned addr = sb + 32768u + (brow + p * 16u) * 128u + bc;
                ldsm4(bh[2*p][0], bh[2*p][1], bh[2*p+1][0], bh[2*p+1][1], addr);
                ldsm4(bl[2*p][0], bl[2*p][1], bl[2*p+1][0], bl[2*p+1][1], addr + 16384u);
            }
            #pragma unroll
            for (int fm = 0; fm < 4; ++fm) {
                unsigned addr = sb + (arow + fm * 16u) * 128u + ac;
                ldsm4(ah[fm][0], ah[fm][1], ah[fm][2], ah[fm][3], addr);
                ldsm4(al[fm][0], al[fm][1], al[fm][2], al[fm][3], addr + 16384u);
            }
            #pragma unroll
            for (int fm = 0; fm < 4; ++fm)
                #pragma unroll
                for (int fn = 0; fn < 4; ++fn)
                    mma16816(acc[fm][fn], ah[fm], bh[fn]);
            #pragma unroll
            for (int fm = 0; fm < 4; ++fm)
                #pragma unroll
                for (int fn = 0; fn < 4; ++fn)
                    mma16816(acc[fm][fn], ah[fm], bl[fn]);
            #pragma unroll
            for (int fm = 0; fm < 4; ++fm)
                #pragma unroll
                for (int fn = 0; fn < 4; ++fn)
                    mma16816(acc[fm][fn], al[fm], bh[fn]);
        }

        // issue next-next stage load (writes stage (kt+2)%3 == (kt-1)%3, whose
        // compute finished before this iteration's __syncthreads)
        if (kt + 2 < KT) {
            int s = kt + 2;
            int slot = s - (s / 3) * 3;
            unsigned sb2 = sbase + (unsigned)slot * STAGE_BYTES + dstRow;
            const __nv_bfloat16* ph = gh + s * 64;
            const __nv_bfloat16* pl = gl + s * 64;
            #pragma unroll
            for (int c = 0; c < 8; ++c) {
                unsigned off = ((unsigned)(c * 16)) ^ swL;
                cpa16(sb2 + matH + off, ph + c * 8);
                cpa16(sb2 + matL + off, pl + c * 8);
            }
        }
        asm volatile("cp.async.commit_group;\n");

        if (++cur == 3) cur = 0;
    }

    // ---- epilogue ----
    const int g = lane >> 2, q = lane & 3;
    #pragma unroll
    for (int fm = 0; fm < 4; ++fm) {
        int row0 = m0 + m_base + fm * 16 + g;
        int row1 = row0 + 8;
        float *p0, *p1;
        if (mode == 0) {
            p0 = C + (size_t)row0 * N;
            p1 = C + (size_t)row1 * N;
        } else {
            p0 = C + (size_t)(row0 & 7) * ((size_t)T_ * V_) + (size_t)(row0 >> 3) * V_;
            p1 = C + (size_t)(row1 & 7) * ((size_t)T_ * V_) + (size_t)(row1 >> 3) * V_;
        }
        #pragma unroll
        for (int fn = 0; fn < 4; ++fn) {
            int col = n0 + n_base + fn * 8 + q * 2;
            float b0 = 0.f, b1 = 0.f;
            if (bias) { b0 = __ldg(&bias[col]); b1 = __ldg(&bias[col + 1]); }
            float2 v0 = make_float2(acc[fm][fn][0] + b0, acc[fm][fn][1] + b1);
            float2 v1 = make_float2(acc[fm][fn][2] + b0, acc[fm][fn][3] + b1);
            *(float2*)(p0 + col) = v0;
            *(float2*)(p1 + col) = v1;
        }
    }
}

// ---------------- persistent recurrence ------------------------------------
#define WH_STRIDE 36
#define H_STRIDE  12
#define REC_FLOATS (1024*WH_STRIDE + 1024*H_STRIDE + 256 + 64 + 64 + 16 + 16 + 128)
#define REC_BYTES  (REC_FLOATS * 4)

// generation barrier: count at bar[0], generation at bar[32] (separate lines).
// Release-arrive orders prior global stores; acquire-spin pairs with it.
__device__ __forceinline__ void grid_barrier(unsigned* bar) {
    __syncthreads();
    if (threadIdx.x == 0) {
        unsigned g;
        asm volatile("ld.acquire.gpu.global.u32 %0, [%1];" : "=r"(g) : "l"(bar + 32));
        unsigned old;
        asm volatile("atom.release.gpu.global.add.u32 %0, [%1], %2;"
                     : "=r"(old) : "l"(bar), "r"(1u));
        if (old == GRID_REC - 1) {
            asm volatile("st.relaxed.gpu.global.u32 [%0], %1;" :: "l"(bar), "r"(0u));
            asm volatile("red.release.gpu.global.add.u32 [%0], %1;" :: "l"(bar + 32), "r"(1u));
        } else {
            unsigned cur2;
            do {
                asm volatile("ld.acquire.gpu.global.u32 %0, [%1];" : "=r"(cur2) : "l"(bar + 32));
            } while (cur2 == g);
        }
    }
    __syncthreads();
}

__device__ __forceinline__ float sigmf(float x) { return 1.f / (1.f + expf(-x)); }

__device__ __forceinline__ unsigned long long pk2(float x, float y) {
    unsigned long long d;
    asm("mov.b64 %0, {%1,%2};" : "=l"(d) : "f"(x), "f"(y));
    return d;
}
__device__ __forceinline__ void upk2(unsigned long long v, float& x, float& y) {
    asm("mov.b64 {%0,%1}, %2;" : "=f"(x), "=f"(y) : "l"(v));
}
__device__ __forceinline__ void fma2(unsigned long long& d, unsigned long long a,
                                     unsigned long long b) {
    asm("fma.rn.f32x2 %0, %1, %2, %0;" : "+l"(d) : "l"(a), "l"(b));
}

__global__ void __launch_bounds__(256, 1)
lstm_rec(const float* __restrict__ xproj,
         const float* __restrict__ Wh,
         const float* __restrict__ gamma, const float* __restrict__ beta,
         float* __restrict__ H,
         float* __restrict__ hfin, float* __restrict__ cfin,
         float* __restrict__ red, unsigned* __restrict__ bar)
{
    extern __shared__ float smem[];
    float* Wh_s = smem;
    float* h_s  = Wh_s + 1024 * WH_STRIDE;
    float* gbuf = h_s + 1024 * H_STRIDE;
    float* craw = gbuf + 256;
    float* hbuf = craw + 64;
    float* gmb  = hbuf + 64;
    float* stat = gmb + 16;
    float* part = stat + 16;

    const int tid = threadIdx.x;
    const int blk = blockIdx.x;
    const int s0  = blk * 8;

    {
        int c = tid & 31, kb = (tid >> 5) * 128;
        int g = c >> 3, u = c & 7;
        const float4* src = (const float4*)(Wh + (size_t)(g * S_ + s0 + u) * S_ + kb);
        #pragma unroll 4
        for (int j = 0; j < 32; ++j) {
            float4 v = __ldg(src + j);
            int k = kb + j * 4;
            Wh_s[(k + 0) * WH_STRIDE + c] = v.x;
            Wh_s[(k + 1) * WH_STRIDE + c] = v.y;
            Wh_s[(k + 2) * WH_STRIDE + c] = v.z;
            Wh_s[(k + 3) * WH_STRIDE + c] = v.w;
        }
    }
    if (tid < 8)  { gmb[tid] = __ldg(&gamma[s0 + tid]); gmb[8 + tid] = __ldg(&beta[s0 + tid]); }
    gbuf[tid] = 0.f;
    __syncthreads();

    const int w = tid >> 5, lane = tid & 31;
    const int cl0 = w * 4;
    const int uu = tid >> 3, bb = tid & 7;

    float cprev = 0.f;

    for (int t = 0; t < T_; ++t) {
        float xpi = 0.f, xpf = 0.f, xpo = 0.f, xpg = 0.f;
        if (tid < 64) {
            const float* xp = xproj + (size_t)(t * B_ + bb) * GS_ + s0 + uu;
            xpi = __ldg(xp + 0 * S_); xpf = __ldg(xp + 1 * S_);
            xpo = __ldg(xp + 2 * S_); xpg = __ldg(xp + 3 * S_);
        }

        if (t > 0) {
            const float* Hsrc = H + (size_t)(t - 1) * (B_ * S_);
            float hv[4][8];
            #pragma unroll
            for (int r = 0; r < 4; ++r)
                #pragma unroll
                for (int b = 0; b < 8; ++b)
                    hv[r][b] = __ldcg(Hsrc + b * S_ + tid + r * 256);

            {
                int par = (t - 1) & 1;
                const float* rp = red + (size_t)par * B_ * GRID_REC * 2;
                if (tid < 64) {
                    int b = tid >> 3, seg = tid & 7;
                    float s1 = 0.f, s2 = 0.f;
                    #pragma unroll
                    for (int q = 0; q < 16; ++q) {
                        float2 v = __ldcg((const float2*)(rp + ((size_t)b * GRID_REC + seg * 16 + q) * 2));
                        s1 += v.x; s2 += v.y;
                    }
                    part[tid * 2] = s1; part[tid * 2 + 1] = s2;
                }
            }
            __syncthreads();
            if (tid < 8) {
                float s1 = 0.f, s2 = 0.f;
                #pragma unroll
                for (int seg = 0; seg < 8; ++seg) {
                    s1 += part[(tid * 8 + seg) * 2];
                    s2 += part[(tid * 8 + seg) * 2 + 1];
                }
                float mu = s1 * (1.f / (float)S_);
                float var = s2 * (1.f / (float)S_) - mu * mu;
                stat[tid] = mu; stat[8 + tid] = rsqrtf(var + EPS_);
            }
            #pragma unroll
            for (int r = 0; r < 4; ++r) {
                int k = tid + r * 256;
                *(float4*)(h_s + k * H_STRIDE)     = make_float4(hv[r][0], hv[r][1], hv[r][2], hv[r][3]);
                *(float4*)(h_s + k * H_STRIDE + 4) = make_float4(hv[r][4], hv[r][5], hv[r][6], hv[r][7]);
            }
            __syncthreads();

            if (tid < 64)
                cprev = (craw[tid] - stat[bb]) * stat[8 + bb] * gmb[uu] + gmb[8 + uu];

            unsigned long long acc2[4][4];
            #pragma unroll
            for (int c = 0; c < 4; ++c)
                #pragma unroll
                for (int p = 0; p < 4; ++p) acc2[c][p] = 0ull;

            #pragma unroll 4
            for (int i = 0; i < 32; ++i) {
                int k = (i << 5) + lane;
                float4 wv = *(const float4*)(Wh_s + k * WH_STRIDE + cl0);
                float4 ha = *(const float4*)(h_s + k * H_STRIDE);
                float4 hb = *(const float4*)(h_s + k * H_STRIDE + 4);
                unsigned long long hp0 = pk2(ha.x, ha.y), hp1 = pk2(ha.z, ha.w);
                unsigned long long hp2 = pk2(hb.x, hb.y), hp3 = pk2(hb.z, hb.w);
                unsigned long long wp;
                wp = pk2(wv.x, wv.x);
                fma2(acc2[0][0], wp, hp0); fma2(acc2[0][1], wp, hp1);
                fma2(acc2[0][2], wp, hp2); fma2(acc2[0][3], wp, hp3);
                wp = pk2(wv.y, wv.y);
                fma2(acc2[1][0], wp, hp0); fma2(acc2[1][1], wp, hp1);
                fma2(acc2[1][2], wp, hp2); fma2(acc2[1][3], wp, hp3);
                wp = pk2(wv.z, wv.z);
                fma2(acc2[2][0], wp, hp0); fma2(acc2[2][1], wp, hp1);
                fma2(acc2[2][2], wp, hp2); fma2(acc2[2][3], wp, hp3);
                wp = pk2(wv.w, wv.w);
                fma2(acc2[3][0], wp, hp0); fma2(acc2[3][1], wp, hp1);
                fma2(acc2[3][2], wp, hp2); fma2(acc2[3][3], wp, hp3);
            }
            #pragma unroll
            for (int c = 0; c < 4; ++c)
                #pragma unroll
                for (int p = 0; p < 4; ++p) {
                    float lo, hi;
                    upk2(acc2[c][p], lo, hi);
                    #pragma unroll
                    for (int o = 16; o > 0; o >>= 1) {
                        lo += __shfl_xor_sync(0xffffffffu, lo, o);
                        hi += __shfl_xor_sync(0xffffffffu, hi, o);
                    }
                    if (lane == 0) {
                        gbuf[(cl0 + c) * 8 + 2 * p]     = lo;
                        gbuf[(cl0 + c) * 8 + 2 * p + 1] = hi;
                    }
                }
            __syncthreads();
        }

        if (tid < 64) {
            float pi = xpi + gbuf[(0 * 8 + uu) * 8 + bb];
            float pf = xpf + gbuf[(1 * 8 + uu) * 8 + bb];
            float po = xpo + gbuf[(2 * 8 + uu) * 8 + bb];
            float pg = xpg + gbuf[(3 * 8 + uu) * 8 + bb];
            float ig = sigmf(pi), fg = sigmf(pf), og = sigmf(po), gg = tanhf(pg);
            float cr = fg * cprev + ig * gg;
            float hh = og * tanhf(cr);
            craw[tid] = cr;
            hbuf[tid] = hh;
            H[(size_t)t * (B_ * S_) + bb * S_ + s0 + uu] = hh;
        }
        __syncthreads();

        if (tid < 8) {
            float s1 = 0.f, s2 = 0.f;
            #pragma unroll
            for (int u = 0; u < 8; ++u) { float v = craw[u * 8 + tid]; s1 += v; s2 += v * v; }
            float2* rp = (float2*)(red + ((size_t)(t & 1) * B_ + tid) * (GRID_REC * 2) + blk * 2);
            *rp = make_float2(s1, s2);
        }

        grid_barrier(bar);
    }

    {
        int par = (T_ - 1) & 1;
        const float* rp = red + (size_t)par * B_ * GRID_REC * 2;
        if (tid < 64) {
            int b = tid >> 3, seg = tid & 7;
            float s1 = 0.f, s2 = 0.f;
            #pragma unroll
            for (int q = 0; q < 16; ++q) {
                float2 v = __ldcg((const float2*)(rp + ((size_t)b * GRID_REC + seg * 16 + q) * 2));
                s1 += v.x; s2 += v.y;
            }
            part[tid * 2] = s1; part[tid * 2 + 1] = s2;
        }
        __syncthreads();
        if (tid < 8) {
            float s1 = 0.f, s2 = 0.f;
            #pragma unroll
            for (int seg = 0; seg < 8; ++seg) {
                s1 += part[(tid * 8 + seg) * 2];
                s2 += part[(tid * 8 + seg) * 2 + 1];
            }
            float mu = s1 * (1.f / (float)S_);
            float var = s2 * (1.f / (float)S_) - mu * mu;
            stat[tid] = mu; stat[8 + tid] = rsqrtf(var + EPS_);
        }
        __syncthreads();
        if (tid < 64) {
            float cn = (craw[tid] - stat[bb]) * stat[8 + bb] * gmb[uu] + gmb[8 + uu];
            cfin[bb * S_ + s0 + uu] = cn;
            hfin[bb * S_ + s0 + uu] = hbuf[tid];
        }
    }
}

// ---------------- host launcher -------------------------------------------
extern "C" void kernel_launch(void* const* d_in, const int* in_sizes, int n_in,
                              void* d_out, int out_size)
{
    (void)in_sizes; (void)n_in; (void)out_size;
    const int*   x     = (const int*)d_in[0];
    const float* emb   = (const float*)d_in[1];
    const float* Wx    = (const float*)d_in[2];
    const float* Wh    = (const float*)d_in[3];
    const float* gamma = (const float*)d_in[4];
    const float* beta  = (const float*)d_in[5];
    const float* Wout  = (const float*)d_in[6];
    const float* bout  = (const float*)d_in[7];
    float* out = (float*)d_out;

    float *xproj, *H0, *H1, *red;
    unsigned* bar;
    __nv_bfloat16 *Wxh, *Wxl, *Wouth, *Woutl, *Ah, *Al;
    cudaGetSymbolAddress((void**)&xproj, d_xproj);
    cudaGetSymbolAddress((void**)&H0,    d_H0);
    cudaGetSymbolAddress((void**)&H1,    d_H1);
    cudaGetSymbolAddress((void**)&red,   d_red);
    cudaGetSymbolAddress((void**)&bar,   d_bar);
    cudaGetSymbolAddress((void**)&Wxh,   d_Wxh);
    cudaGetSymbolAddress((void**)&Wxl,   d_Wxl);
    cudaGetSymbolAddress((void**)&Wouth, d_Wouth);
    cudaGetSymbolAddress((void**)&Woutl, d_Woutl);
    cudaGetSymbolAddress((void**)&Ah,    d_Ah);
    cudaGetSymbolAddress((void**)&Al,    d_Al);

    cudaFuncSetAttribute(lstm_rec, cudaFuncAttributeMaxDynamicSharedMemorySize, REC_BYTES);
    cudaFuncSetAttribute(gemm_tc, cudaFuncAttributeMaxDynamicSharedMemorySize, GEMM_SMEM);

    float* h_out = out + (size_t)B_ * T_ * V_;
    float* c_out = h_out + (size_t)L_ * B_ * S_;

    const size_t wstride = (size_t)GS_ * S_;
    const size_t wstride_bf = (size_t)GS_ * S_;

    init_bar_k<<<1, 1>>>(bar);

    // pre-split weights
    cvt_split_k<<<(L_ * GS_ * S_ / 4 + 255) / 256, 256>>>(Wx, Wxh, Wxl, L_ * GS_ * S_ / 4);
    cvt_split_k<<<(V_ * S_ / 4 + 255) / 256, 256>>>(Wout, Wouth, Woutl, V_ * S_ / 4);

    // layer 0: A = gathered+split emb rows; xproj = A @ Wx0^T
    cvt_gather_k<<<(T_ * B_ * S_ / 4 + 255) / 256, 256>>>(emb, x, Ah, Al);
    gemm_tc<<<dim3((T_ * B_) / 128, GS_ / 128), 256, GEMM_SMEM>>>(
        T_ * B_, GS_, S_, Ah, Al, Wxh, Wxl, nullptr, xproj, 0);
    lstm_rec<<<GRID_REC, 256, REC_BYTES>>>(
        xproj, Wh, gamma, beta, H0, h_out, c_out, red, bar);

    // layer 1: A = split(H0); xproj = A @ Wx1^T
    cvt_split_k<<<(T_ * B_ * S_ / 4 + 255) / 256, 256>>>(H0, Ah, Al, T_ * B_ * S_ / 4);
    gemm_tc<<<dim3((T_ * B_) / 128, GS_ / 128), 256, GEMM_SMEM>>>(
        T_ * B_, GS_, S_, Ah, Al, Wxh + wstride_bf, Wxl + wstride_bf, nullptr, xproj, 0);
    lstm_rec<<<GRID_REC, 256, REC_BYTES>>>(
        xproj, Wh + wstride, gamma + S_, beta + S_, H1,
        h_out + (size_t)B_ * S_, c_out + (size_t)B_ * S_, red, bar);

    // logits: out = H1 @ Wout^T + bout
    cvt_split_k<<<(T_ * B_ * S_ / 4 + 255) / 256, 256>>>(H1, Ah, Al, T_ * B_ * S_ / 4);
    gemm_tc<<<dim3((T_ * B_) / 128, V_ / 128), 256, GEMM_SMEM>>>(
        T_ * B_, V_, S_, Ah, Al, Wouth, Woutl, bout, out, 1);
}